// round 14
// baseline (speedup 1.0000x reference)
#include <cuda_runtime.h>
#include <cuda_bf16.h>
#include <cuda_fp16.h>
#include <math.h>
#include <stdint.h>

#define BATCH 2
#define SEQ   2048
#define EMB   1024
#define NH    16
#define DH    64
#define M_TOT (BATCH*SEQ)   // 4096

// ---------------------------------------------------------------------------
// Device scratch
// ---------------------------------------------------------------------------
__device__ __nv_bfloat16 g_Xhi[M_TOT*EMB];
__device__ __nv_bfloat16 g_Xlo[M_TOT*EMB];
__device__ __half        g_Xf[M_TOT*EMB];
__device__ __nv_bfloat16 g_Whi[2*EMB*EMB];   // Wq, Wk (bf16 hi)
__device__ __nv_bfloat16 g_Wlo[2*EMB*EMB];   // Wq, Wk (bf16 lo)
__device__ __half        g_Wf[2*EMB*EMB];    // Wv, Wo (single f16)
__device__ __nv_bfloat16 g_Qhi[BATCH*NH*SEQ*DH];
__device__ __nv_bfloat16 g_Qlo[BATCH*NH*SEQ*DH];
__device__ __nv_bfloat16 g_Khi[BATCH*NH*SEQ*DH];
__device__ __nv_bfloat16 g_Klo[BATCH*NH*SEQ*DH];
__device__ __half        g_Vf[BATCH*NH*SEQ*DH];   // head-major, single f16
__device__ __half        g_Of[M_TOT*EMB];         // row-major, single f16

// ---------------------------------------------------------------------------
// PTX helpers (portable sm_80-class only)
// ---------------------------------------------------------------------------
__device__ __forceinline__ uint32_t smem_u32(const void* p) {
    uint32_t a;
    asm("{ .reg .u64 t; cvta.to.shared.u64 t, %1; cvt.u32.u64 %0, t; }" : "=r"(a) : "l"(p));
    return a;
}

#define CP_ASYNC16(dst, src) \
    asm volatile("cp.async.cg.shared.global [%0], [%1], 16;" :: "r"(dst), "l"(src))
#define CP_COMMIT() asm volatile("cp.async.commit_group;")
#define CP_WAIT0()  asm volatile("cp.async.wait_group 0;")
#define CP_WAIT1()  asm volatile("cp.async.wait_group 1;")

#define LDSM4(r, addr) \
    asm volatile("ldmatrix.sync.aligned.m8n8.x4.shared.b16 {%0,%1,%2,%3}, [%4];" \
        : "=r"((r)[0]), "=r"((r)[1]), "=r"((r)[2]), "=r"((r)[3]) : "r"(addr))
#define LDSM4T(r, addr) \
    asm volatile("ldmatrix.sync.aligned.m8n8.x4.trans.shared.b16 {%0,%1,%2,%3}, [%4];" \
        : "=r"((r)[0]), "=r"((r)[1]), "=r"((r)[2]), "=r"((r)[3]) : "r"(addr))

#define MMA_BF16(c, a, b0v, b1v) \
    asm volatile("mma.sync.aligned.m16n8k16.row.col.f32.bf16.bf16.f32 " \
        "{%0,%1,%2,%3}, {%4,%5,%6,%7}, {%8,%9}, {%0,%1,%2,%3};" \
        : "+f"((c)[0]), "+f"((c)[1]), "+f"((c)[2]), "+f"((c)[3]) \
        : "r"((a)[0]), "r"((a)[1]), "r"((a)[2]), "r"((a)[3]), "r"(b0v), "r"(b1v))

#define MMA_F16(c, a, b0v, b1v) \
    asm volatile("mma.sync.aligned.m16n8k16.row.col.f32.f16.f16.f32 " \
        "{%0,%1,%2,%3}, {%4,%5,%6,%7}, {%8,%9}, {%0,%1,%2,%3};" \
        : "+f"((c)[0]), "+f"((c)[1]), "+f"((c)[2]), "+f"((c)[3]) \
        : "r"((a)[0]), "r"((a)[1]), "r"((a)[2]), "r"((a)[3]), "r"(b0v), "r"(b1v))

__device__ __forceinline__ float fast_exp2(float x) {
    float r;
    asm("ex2.approx.ftz.f32 %0, %1;" : "=f"(r) : "f"(x));
    return r;
}

__device__ __forceinline__ uint32_t packbf2(float lo, float hi) {
    uint32_t r;
    asm("cvt.rn.bf16x2.f32 %0, %1, %2;" : "=r"(r) : "f"(hi), "f"(lo));
    return r;
}
__device__ __forceinline__ float bflo(uint32_t u) { return __uint_as_float(u << 16); }
__device__ __forceinline__ float bfhi(uint32_t u) { return __uint_as_float(u & 0xFFFF0000u); }

__device__ __forceinline__ uint32_t packh2(float a, float b) {
    __half2 h = __floats2half2_rn(a, b);
    return *(uint32_t*)&h;
}
__device__ __forceinline__ float hsum2(uint32_t u) {
    __half2 h = *(__half2*)&u;
    float2 f = __half22float2(h);
    return f.x + f.y;
}

__device__ __forceinline__ uint32_t swz(uint32_t off) {   // SW128 for 128B rows
    return off ^ ((off >> 3) & 0x70);
}

// ---------------------------------------------------------------------------
// Fused conversion kernel: blocks [0,2048) convert X; [2048,2560) convert W.
// ---------------------------------------------------------------------------
__global__ void convert_all(const float* __restrict__ X,
                            const float* __restrict__ W0, const float* __restrict__ W1,
                            const float* __restrict__ W2, const float* __restrict__ W3)
{
    __shared__ float Wsm[64][129];
    const int tid = threadIdx.x;
    if (blockIdx.x < 2048) {
        int gid = blockIdx.x * 256 + tid;
        size_t base = (size_t)gid * 8;
        float4 v0 = *(const float4*)&X[base];
        float4 v1 = *(const float4*)&X[base + 4];
        float vs[8] = {v0.x, v0.y, v0.z, v0.w, v1.x, v1.y, v1.z, v1.w};
        __nv_bfloat16 h[8], l[8];
        __half f[8];
#pragma unroll
        for (int i = 0; i < 8; i++) {
            h[i] = __float2bfloat16(vs[i]);
            l[i] = __float2bfloat16(vs[i] - __bfloat162float(h[i]));
            f[i] = __float2half_rn(vs[i]);
        }
        *(uint4*)&g_Xhi[base] = *(uint4*)h;
        *(uint4*)&g_Xlo[base] = *(uint4*)l;
        *(uint4*)&g_Xf[base]  = *(uint4*)f;
        return;
    }

    int bi = blockIdx.x - 2048;          // 0..511
    int w = bi >> 7;
    int rest = bi & 127;
    int ntile = rest >> 4;
    int kc = rest & 15;
    const float* W = (w == 0) ? W0 : (w == 1) ? W1 : (w == 2) ? W2 : W3;

#pragma unroll
    for (int i = 0; i < 32; i++) {
        int lin = i * 256 + tid;
        int kr = lin >> 7;
        int nc = lin & 127;
        Wsm[kr][nc] = W[(size_t)(kc * 64 + kr) * EMB + ntile * 128 + nc];
    }
    __syncthreads();

#pragma unroll
    for (int j = 0; j < 4; j++) {
        int lin = j * 256 + tid;
        int nin = lin >> 3;
        int g = lin & 7;
        float vs[8];
#pragma unroll
        for (int i = 0; i < 8; i++) vs[i] = Wsm[g * 8 + i][nin];
        if (w < 2) {
            size_t base = ((size_t)(w * EMB + ntile * 128 + nin)) * EMB + kc * 64 + g * 8;
            __nv_bfloat16 h[8], l[8];
#pragma unroll
            for (int i = 0; i < 8; i++) {
                h[i] = __float2bfloat16(vs[i]);
                l[i] = __float2bfloat16(vs[i] - __bfloat162float(h[i]));
            }
            *(uint4*)&g_Whi[base] = *(uint4*)h;
            *(uint4*)&g_Wlo[base] = *(uint4*)l;
        } else {
            size_t base = ((size_t)((w - 2) * EMB + ntile * 128 + nin)) * EMB + kc * 64 + g * 8;
            __half h[8];
#pragma unroll
            for (int i = 0; i < 8; i++) h[i] = __float2half_rn(vs[i]);
            *(uint4*)&g_Wf[base] = *(uint4*)h;
        }
    }
}

// ---------------------------------------------------------------------------
// Merged QKV projection: 768 CTAs, 256 thr, CTA tile 128x128, BK=64,
// SW128-swizzled 128B smem rows, 3-stage cp.async. (r12 — frozen)
// ---------------------------------------------------------------------------
#define PA_TILE 16384                    // 128 rows * 128B
#define PSTAGE_QK (4*PA_TILE)            // 65536
#define PSTAGE_V  (2*PA_TILE)            // 32768
#define PROJ_SMEM (3*PSTAGE_QK)          // 196608

__global__ __launch_bounds__(256, 1)
void proj_all()
{
    extern __shared__ __align__(128) char smem[];
    const uint32_t sb = smem_u32(smem);
    const int tid = threadIdx.x, lane = tid & 31, wid = tid >> 5;
    const int wm = wid & 3, wn = wid >> 2;

    const uint32_t aBase = (wm * 32 + (lane & 15)) * 128 + (lane >> 4) * 16;
    const uint32_t bBase = (wn * 64 + (lane & 7) + ((lane >> 4) << 3)) * 128
                         + ((lane >> 3) & 1) * 16;
    const int lrow = tid >> 3;
    const int lseg = tid & 7;

    float acc[2][8][4];
#pragma unroll
    for (int i = 0; i < 2; i++)
#pragma unroll
        for (int j = 0; j < 8; j++)
#pragma unroll
            for (int q = 0; q < 4; q++) acc[i][j][q] = 0.0f;

    if (blockIdx.x < 512) {
        const int z = blockIdx.x >> 8;
        const int r = blockIdx.x & 255;
        const int bx = r & 7, by = r >> 3;

        const __nv_bfloat16* Bhi = g_Whi + (size_t)z * EMB * EMB;
        const __nv_bfloat16* Blo = g_Wlo + (size_t)z * EMB * EMB;

        auto load_stage = [&](int c, int slot) {
            const int k0 = c * 64;
            const uint32_t st = sb + slot * PSTAGE_QK;
#pragma unroll
            for (int i = 0; i < 4; i++) {
                const int rr = i * 32 + lrow;
                const uint32_t d = swz(rr * 128 + lseg * 16);
                const size_t gi = (size_t)(by * 128 + rr) * EMB + k0 + lseg * 8;
                const size_t gw = (size_t)(bx * 128 + rr) * EMB + k0 + lseg * 8;
                CP_ASYNC16(st + d,               g_Xhi + gi);
                CP_ASYNC16(st + PA_TILE + d,     g_Xlo + gi);
                CP_ASYNC16(st + 2*PA_TILE + d,   Bhi + gw);
                CP_ASYNC16(st + 3*PA_TILE + d,   Blo + gw);
            }
            CP_COMMIT();
        };

        load_stage(0, 0);
        load_stage(1, 1);

        for (int c = 0; c < 16; c++) {
            CP_WAIT1();
            __syncthreads();
            if (c + 2 < 16) load_stage(c + 2, (c + 2) % 3);
            const uint32_t st = sb + (c % 3) * PSTAGE_QK;
            const uint32_t Ah = st, Al = st + PA_TILE;
            const uint32_t Bh = st + 2*PA_TILE, Bl = st + 3*PA_TILE;

#pragma unroll
            for (int kc = 0; kc < 4; kc++) {
                const uint32_t kB = kc * 32;
                uint32_t ah[2][4], al[2][4], bh[4][4], bl[4][4];
#pragma unroll
                for (int ni = 0; ni < 4; ni++) {
                    LDSM4(bh[ni], Bh + swz(bBase + ni * 2048 + kB));
                    LDSM4(bl[ni], Bl + swz(bBase + ni * 2048 + kB));
                }
#pragma unroll
                for (int mi = 0; mi < 2; mi++)
                    LDSM4(ah[mi], Ah + swz(aBase + mi * 2048 + kB));
#pragma unroll
                for (int mi = 0; mi < 2; mi++)
#pragma unroll
                    for (int ni = 0; ni < 4; ni++) {
                        MMA_BF16(acc[mi][2*ni],   ah[mi], bh[ni][0], bh[ni][1]);
                        MMA_BF16(acc[mi][2*ni+1], ah[mi], bh[ni][2], bh[ni][3]);
                        MMA_BF16(acc[mi][2*ni],   ah[mi], bl[ni][0], bl[ni][1]);
                        MMA_BF16(acc[mi][2*ni+1], ah[mi], bl[ni][2], bl[ni][3]);
                    }
#pragma unroll
                for (int mi = 0; mi < 2; mi++)
                    LDSM4(al[mi], Al + swz(aBase + mi * 2048 + kB));
#pragma unroll
                for (int mi = 0; mi < 2; mi++)
#pragma unroll
                    for (int ni = 0; ni < 4; ni++) {
                        MMA_BF16(acc[mi][2*ni],   al[mi], bh[ni][0], bh[ni][1]);
                        MMA_BF16(acc[mi][2*ni+1], al[mi], bh[ni][2], bh[ni][3]);
                    }
            }
        }
        __syncthreads();

        float* Cs = (float*)smem;            // [128][132]
#pragma unroll
        for (int mi = 0; mi < 2; mi++)
#pragma unroll
            for (int nf = 0; nf < 8; nf++) {
                const int r0 = wm * 32 + mi * 16 + (lane >> 2);
                const int col = wn * 64 + nf * 8 + (lane & 3) * 2;
                *(float2*)&Cs[r0 * 132 + col]       = make_float2(acc[mi][nf][0], acc[mi][nf][1]);
                *(float2*)&Cs[(r0 + 8) * 132 + col] = make_float2(acc[mi][nf][2], acc[mi][nf][3]);
            }
        __syncthreads();

#pragma unroll
        for (int it = 0; it < 16; it++) {
            const int lin = it * 256 + tid;
            const int rr = lin >> 5;
            const int cg = (lin & 31) * 4;
            float4 v = *(const float4*)&Cs[rr * 132 + cg];
            const int m = by * 128 + rr;
            const int n = bx * 128 + cg;
            const int b = m >> 11, s = m & 2047, h = n >> 6, d = n & 63;
            __nv_bfloat16* dh = (z == 0) ? g_Qhi : g_Khi;
            __nv_bfloat16* dl = (z == 0) ? g_Qlo : g_Klo;
            uint32_t u0 = packbf2(v.x, v.y), u1 = packbf2(v.z, v.w);
            uint32_t l0 = packbf2(v.x - bflo(u0), v.y - bfhi(u0));
            uint32_t l1 = packbf2(v.z - bflo(u1), v.w - bfhi(u1));
            size_t addr = (((size_t)(b * NH + h)) * SEQ + s) * DH + d;
            *(uint2*)&dh[addr] = make_uint2(u0, u1);
            *(uint2*)&dl[addr] = make_uint2(l0, l1);
        }
    } else {
        const int j = blockIdx.x - 512;
        const int bx = j & 7, by = j >> 3;
        const __half* Bf = g_Wf;

        auto load_stage = [&](int c, int slot) {
            const int k0 = c * 64;
            const uint32_t st = sb + slot * PSTAGE_V;
#pragma unroll
            for (int i = 0; i < 4; i++) {
                const int rr = i * 32 + lrow;
                const uint32_t d = swz(rr * 128 + lseg * 16);
                CP_ASYNC16(st + d,
                           g_Xf + (size_t)(by * 128 + rr) * EMB + k0 + lseg * 8);
                CP_ASYNC16(st + PA_TILE + d,
                           Bf + (size_t)(bx * 128 + rr) * EMB + k0 + lseg * 8);
            }
            CP_COMMIT();
        };

        load_stage(0, 0);
        load_stage(1, 1);

        for (int c = 0; c < 16; c++) {
            CP_WAIT1();
            __syncthreads();
            if (c + 2 < 16) load_stage(c + 2, (c + 2) % 3);
            const uint32_t st = sb + (c % 3) * PSTAGE_V;
            const uint32_t At = st, Bt = st + PA_TILE;

#pragma unroll
            for (int kc = 0; kc < 4; kc++) {
                const uint32_t kB = kc * 32;
                uint32_t ar[2][4], bh[4][4];
#pragma unroll
                for (int ni = 0; ni < 4; ni++)
                    LDSM4(bh[ni], Bt + swz(bBase + ni * 2048 + kB));
#pragma unroll
                for (int mi = 0; mi < 2; mi++)
                    LDSM4(ar[mi], At + swz(aBase + mi * 2048 + kB));
#pragma unroll
                for (int mi = 0; mi < 2; mi++)
#pragma unroll
                    for (int ni = 0; ni < 4; ni++) {
                        MMA_F16(acc[mi][2*ni],   ar[mi], bh[ni][0], bh[ni][1]);
                        MMA_F16(acc[mi][2*ni+1], ar[mi], bh[ni][2], bh[ni][3]);
                    }
            }
        }
        __syncthreads();

        float* Cs = (float*)smem;            // [128][132]
#pragma unroll
        for (int mi = 0; mi < 2; mi++)
#pragma unroll
            for (int nf = 0; nf < 8; nf++) {
                const int r0 = wm * 32 + mi * 16 + (lane >> 2);
                const int col = wn * 64 + nf * 8 + (lane & 3) * 2;
                *(float2*)&Cs[r0 * 132 + col]       = make_float2(acc[mi][nf][0], acc[mi][nf][1]);
                *(float2*)&Cs[(r0 + 8) * 132 + col] = make_float2(acc[mi][nf][2], acc[mi][nf][3]);
            }
        __syncthreads();

#pragma unroll
        for (int it = 0; it < 16; it++) {
            const int lin = it * 256 + tid;
            const int rr = lin >> 5;
            const int cg = (lin & 31) * 4;
            float4 v = *(const float4*)&Cs[rr * 132 + cg];
            const int m = by * 128 + rr;
            const int n = bx * 128 + cg;
            const int b = m >> 11, s = m & 2047, h = n >> 6, d = n & 63;
            size_t addr = (((size_t)(b * NH + h)) * SEQ + s) * DH + d;
            *(uint2*)&g_Vf[addr] = make_uint2(packh2(v.x, v.y), packh2(v.z, v.w));
        }
    }
}

// ---------------------------------------------------------------------------
// gemm_o: single-f16 GEMM (r12 — frozen).
// ---------------------------------------------------------------------------
#define GO_STAGE (2*PA_TILE)             // 32768
#define GO_SMEM  (3*GO_STAGE)            // 98304

__global__ __launch_bounds__(256, 2)
void gemm_o(float* __restrict__ Cout)
{
    extern __shared__ __align__(128) char smem[];
    const uint32_t sb = smem_u32(smem);
    const int tid = threadIdx.x, lane = tid & 31, wid = tid >> 5;
    const int wm = wid & 3, wn = wid >> 2;
    const int bx = blockIdx.x, by = blockIdx.y;

    const __half* Bf = g_Wf + (size_t)EMB * EMB;   // Wo

    const uint32_t aBase = (wm * 32 + (lane & 15)) * 128 + (lane >> 4) * 16;
    const uint32_t bBase = (wn * 64 + (lane & 7) + ((lane >> 4) << 3)) * 128
                         + ((lane >> 3) & 1) * 16;
    const int lrow = tid >> 3;
    const int lseg = tid & 7;

    float acc[2][8][4];
#pragma unroll
    for (int i = 0; i < 2; i++)
#pragma unroll
        for (int j = 0; j < 8; j++)
#pragma unroll
            for (int q = 0; q < 4; q++) acc[i][j][q] = 0.0f;

    auto load_stage = [&](int c, int slot) {
        const int k0 = c * 64;
        const uint32_t st = sb + slot * GO_STAGE;
#pragma unroll
        for (int i = 0; i < 4; i++) {
            const int rr = i * 32 + lrow;
            const uint32_t d = swz(rr * 128 + lseg * 16);
            CP_ASYNC16(st + d,
                       g_Of + (size_t)(by * 128 + rr) * EMB + k0 + lseg * 8);
            CP_ASYNC16(st + PA_TILE + d,
                       Bf + (size_t)(bx * 128 + rr) * EMB + k0 + lseg * 8);
        }
        CP_COMMIT();
    };

    load_stage(0, 0);
    load_stage(1, 1);

    for (int c = 0; c < 16; c++) {
        CP_WAIT1();
        __syncthreads();
        if (c + 2 < 16) load_stage(c + 2, (c + 2) % 3);
        const uint32_t st = sb + (c % 3) * GO_STAGE;
        const uint32_t At = st, Bt = st + PA_TILE;

#pragma unroll
        for (int kc = 0; kc < 4; kc++) {
            const uint32_t kB = kc * 32;
            uint32_t ar[2][4], bh[4][4];
#pragma unroll
            for (int ni = 0; ni < 4; ni++)
                LDSM4(bh[ni], Bt + swz(bBase + ni * 2048 + kB));
#pragma unroll
            for (int mi = 0; mi < 2; mi++)
                LDSM4(ar[mi], At + swz(aBase + mi * 2048 + kB));
#pragma unroll
            for (int mi = 0; mi < 2; mi++)
#pragma unroll
                for (int ni = 0; ni < 4; ni++) {
                    MMA_F16(acc[mi][2*ni],   ar[mi], bh[ni][0], bh[ni][1]);
                    MMA_F16(acc[mi][2*ni+1], ar[mi], bh[ni][2], bh[ni][3]);
                }
        }
    }
    __syncthreads();

    float* Cs = (float*)smem;            // [128][132]
#pragma unroll
    for (int mi = 0; mi < 2; mi++)
#pragma unroll
        for (int nf = 0; nf < 8; nf++) {
            const int r0 = wm * 32 + mi * 16 + (lane >> 2);
            const int col = wn * 64 + nf * 8 + (lane & 3) * 2;
            *(float2*)&Cs[r0 * 132 + col]       = make_float2(acc[mi][nf][0], acc[mi][nf][1]);
            *(float2*)&Cs[(r0 + 8) * 132 + col] = make_float2(acc[mi][nf][2], acc[mi][nf][3]);
        }
    __syncthreads();

#pragma unroll
    for (int it = 0; it < 16; it++) {
        const int lin = it * 256 + tid;
        const int rr = lin >> 5;
        const int cg = (lin & 31) * 4;
        float4 v = *(const float4*)&Cs[rr * 132 + cg];
        const int m = by * 128 + rr;
        const int n = bx * 128 + cg;
        *(float4*)&Cout[(size_t)m * EMB + n] = v;
    }
}

// ---------------------------------------------------------------------------
// Flash attention v3: CTA = 256 q-rows, 32 q-rows/warp (two m16 groups),
// KV tiles 64 rows double-buffered. K/V smem bytes per (q,k) element HALVED
// vs r12 (crossbar-bound kernel). Q hi resident in regs; Q lo reloaded per kc.
// QK bf16x3; PV f16 P x f16 V (l over rounded P).
// smem: Qhi 32KB + Qlo 32KB + 2 x 24KB KV = 112KB.
// ---------------------------------------------------------------------------
#define KV3_STAGE 24576      // Kh 8KB + Kl 8KB + Vf 8KB
#define FL_SMEM (65536 + 2*KV3_STAGE)   // 114688
#define CEXP 0.18033688f     // 0.125 * log2(e)

__global__ __launch_bounds__(256, 1)
void flash_mma()
{
    const int qt = (int)gridDim.x - 1 - blockIdx.x;   // heavy tiles first
    const int h = blockIdx.y, b = blockIdx.z;
    const int tid = threadIdx.x, lane = tid & 31, w = tid >> 5;
    extern __shared__ __align__(128) char smf[];
    const uint32_t sb = smem_u32(smf);
    const uint32_t Qh_ = sb, Ql_ = sb + 32768;

    const size_t head = ((size_t)(b * NH + h)) * SEQ * DH;
    const __nv_bfloat16* Qhg = g_Qhi + head;
    const __nv_bfloat16* Qlg = g_Qlo + head;
    const __nv_bfloat16* Khg = g_Khi + head;
    const __nv_bfloat16* Klg = g_Klo + head;
    const __half*        Vfg = g_Vf  + head;
    const int qbase = qt * 256;
    const int nkt = 4 * qt + 4;          // 64-row kv tiles

    // Q tile (256 x 64) hi+lo
#pragma unroll
    for (int i = 0; i < 8; i++) {
        int lin = i * 256 + tid;
        int r = lin >> 3, c = lin & 7;
        uint32_t off = swz(r * 128 + c * 16);
        CP_ASYNC16(Qh_ + off, Qhg + (size_t)(qbase + r) * 64 + c * 8);
        CP_ASYNC16(Ql_ + off, Qlg + (size_t)(qbase + r) * 64 + c * 8);
    }
    CP_COMMIT();

    auto load_kv = [&](int jt, int slot) {
        const uint32_t st = sb + 65536 + slot * KV3_STAGE;
#pragma unroll
        for (int i = 0; i < 2; i++) {
            int lin = i * 256 + tid;
            int r = lin >> 3, c = lin & 7;     // r 0..63
            uint32_t off = swz(r * 128 + c * 16);
            size_t gidx = (size_t)(jt * 64 + r) * 64 + c * 8;
            CP_ASYNC16(st + off,            Khg + gidx);
            CP_ASYNC16(st + 8192 + off,     Klg + gidx);
            CP_ASYNC16(st + 16384 + off,    Vfg + gidx);
        }
        CP_COMMIT();
    };

    load_kv(0, 0);
    CP_WAIT1();          // Q ready
    __syncthreads();

    // Q hi resident (2 m16 groups x 4 kc); Q lo reloaded per kc in mainloop.
    uint32_t qh[2][4][4];
    const uint32_t qr0 = (w * 32 + (lane & 15)) * 128 + (lane >> 4) * 16;
#pragma unroll
    for (int mi = 0; mi < 2; mi++)
#pragma unroll
        for (int kc = 0; kc < 4; kc++)
            LDSM4(qh[mi][kc], Qh_ + swz(qr0 + mi * 2048 + kc * 32));

    float o_[2][8][4];
#pragma unroll
    for (int mi = 0; mi < 2; mi++)
#pragma unroll
        for (int i = 0; i < 8; i++)
#pragma unroll
            for (int j = 0; j < 4; j++) o_[mi][i][j] = 0.0f;
    float mrow[2][2] = {{-3e38f, -3e38f}, {-3e38f, -3e38f}};
    float lrow[2][2] = {{0.0f, 0.0f}, {0.0f, 0.0f}};

    // global q-row indices per mi group
    const int rA0 = qbase + w * 32 + (lane >> 2);        // mi=0, halves +0/+8
    const int rA1 = rA0 + 16;                            // mi=1
    const uint32_t kOffBase = ((lane & 7) + ((lane >> 4) << 3)) * 128 + ((lane >> 3) & 1) * 16;
    const uint32_t vOffBase = (lane & 15) * 128 + (lane >> 4) * 16;

    for (int jt = 0; jt < nkt; jt++) {
        CP_WAIT0();                       // kv(jt) complete
        __syncthreads();
        if (jt + 1 < nkt) load_kv(jt + 1, (jt + 1) & 1);
        const uint32_t st = sb + 65536 + (jt & 1) * KV3_STAGE;
        const uint32_t Kh_ = st, Kl_ = st + 8192, Vf_ = st + 16384;

        float s_[2][8][4];
#pragma unroll
        for (int mi = 0; mi < 2; mi++)
#pragma unroll
            for (int i = 0; i < 8; i++)
#pragma unroll
                for (int j = 0; j < 4; j++) s_[mi][i][j] = 0.0f;

        // ---- QK^T (bf16x3): K frags shared across both m16 groups ----
#pragma unroll
        for (int kc = 0; kc < 4; kc++) {
            uint32_t qlr[2][4];
#pragma unroll
            for (int mi = 0; mi < 2; mi++)
                LDSM4(qlr[mi], Ql_ + swz(qr0 + mi * 2048 + kc * 32));
#pragma unroll
            for (int tp = 0; tp < 2; tp++) {
                const uint32_t addrA = swz((2*tp)   * 2048 + kOffBase + kc * 32);
                const uint32_t addrB = swz((2*tp+1) * 2048 + kOffBase + kc * 32);
                uint32_t bha[4], bla[4], bhb[4], blb[4];
                LDSM4(bha, Kh_ + addrA);
                LDSM4(bhb, Kh_ + addrB);
                LDSM4(bla, Kl_ + addrA);
                LDSM4(blb, Kl_ + addrB);
#pragma unroll
                for (int mi = 0; mi < 2; mi++) {
                    MMA_BF16(s_[mi][4*tp],     qh[mi][kc], bha[0], bha[1]);
                    MMA_BF16(s_[mi][4*tp + 1], qh[mi][kc], bha[2], bha[3]);
                    MMA_BF16(s_[mi][4*tp + 2], qh[mi][kc], bhb[0], bhb[1]);
                    MMA_BF16(s_[mi][4*tp + 3], qh[mi][kc], bhb[2], bhb[3]);
                    MMA_BF16(s_[mi][4*tp],     qlr[mi],    bha[0], bha[1]);
                    MMA_BF16(s_[mi][4*tp + 1], qlr[mi],    bha[2], bha[3]);
                    MMA_BF16(s_[mi][4*tp + 2], qlr[mi],    bhb[0], bhb[1]);
                    MMA_BF16(s_[mi][4*tp + 3], qlr[mi],    bhb[2], bhb[3]);
                    MMA_BF16(s_[mi][4*tp],     qh[mi][kc], bla[0], bla[1]);
                    MMA_BF16(s_[mi][4*tp + 1], qh[mi][kc], bla[2], bla[3]);
                    MMA_BF16(s_[mi][4*tp + 2], qh[mi][kc], blb[0], blb[1]);
                    MMA_BF16(s_[mi][4*tp + 3], qh[mi][kc], blb[2], blb[3]);
                }
            }
        }

        // ---- causal mask (tiles overlapping/above the diagonal) ----
        if (jt >= 4 * qt) {
#pragma unroll
            for (int mi = 0; mi < 2; mi++) {
                const int rA = (mi == 0) ? rA0 : rA1;
                const int rB = rA + 8;
#pragma unroll
                for (int nf = 0; nf < 8; nf++) {
                    const int colg = jt * 64 + nf * 8 + (lane & 3) * 2;
                    if (colg     > rA) s_[mi][nf][0] = -3e38f;
                    if (colg + 1 > rA) s_[mi][nf][1] = -3e38f;
                    if (colg     > rB) s_[mi][nf][2] = -3e38f;
                    if (colg + 1 > rB) s_[mi][nf][3] = -3e38f;
                }
            }
        }

        // ---- online softmax + PV per m16 group ----
#pragma unroll
        for (int mi = 0; mi < 2; mi++) {
            float mx0 = -3e38f, mx1 = -3e38f;
#pragma unroll
            for (int nf = 0; nf < 8; nf++) {
                mx0 = fmaxf(mx0, fmaxf(s_[mi][nf][0], s_[mi][nf][1]));
                mx1 = fmaxf(mx1, fmaxf(s_[mi][nf][2], s_[mi][nf][3]));
            }
            mx0 = fmaxf(mx0, __shfl_xor_sync(0xffffffffu, mx0, 1));
            mx0 = fmaxf(mx0, __shfl_xor_sync(0xffffffffu, mx0, 2));
            mx1 = fmaxf(mx1, __shfl_xor_sync(0xffffffffu, mx1, 1));
            mx1 = fmaxf(mx1, __shfl_xor_sync(0xffffffffu, mx1, 2));
            const float mn0 = fmaxf(mrow[mi][0], mx0);
            const float mn1 = fmaxf(mrow[mi][1], mx1);
            const float c0 = fast_exp2((mrow[mi][0] - mn0) * CEXP);
            const float c1 = fast_exp2((mrow[mi][1] - mn1) * CEXP);
            mrow[mi][0] = mn0; mrow[mi][1] = mn1;

            uint32_t ph[4][4];
            float rs0 = 0.0f, rs1 = 0.0f;
#pragma unroll
            for (int j = 0; j < 4; j++) {
                const float p00 = fast_exp2((s_[mi][2*j][0]   - mn0) * CEXP);
                const float p01 = fast_exp2((s_[mi][2*j][1]   - mn0) * CEXP);
                const float p10 = fast_exp2((s_[mi][2*j][2]   - mn1) * CEXP);
                const float p11 = fast_exp2((s_[mi][2*j][3]   - mn1) * CEXP);
                const float p20 = fast_exp2((s_[mi][2*j+1][0] - mn0) * CEXP);
                const float p21 = fast_exp2((s_[mi][2*j+1][1] - mn0) * CEXP);
                const float p30 = fast_exp2((s_[mi][2*j+1][2] - mn1) * CEXP);
                const float p31 = fast_exp2((s_[mi][2*j+1][3] - mn1) * CEXP);
                ph[j][0] = packh2(p00, p01);
                ph[j][1] = packh2(p10, p11);
                ph[j][2] = packh2(p20, p21);
                ph[j][3] = packh2(p30, p31);
                rs0 += hsum2(ph[j][0]) + hsum2(ph[j][2]);
                rs1 += hsum2(ph[j][1]) + hsum2(ph[j][3]);
            }
            rs0 += __shfl_xor_sync(0xffffffffu, rs0, 1);
            rs0 += __shfl_xor_sync(0xffffffffu, rs0, 2);
            rs1 += __shfl_xor_sync(0xffffffffu, rs1, 1);
            rs1 += __shfl_xor_sync(0xffffffffu, rs1, 2);
            lrow[mi][0] = lrow[mi][0] * c0 + rs0;
            lrow[mi][1] = lrow[mi][1] * c1 + rs1;
#pragma unroll
            for (int nf = 0; nf < 8; nf++) {
                o_[mi][nf][0] *= c0; o_[mi][nf][1] *= c0;
                o_[mi][nf][2] *= c1; o_[mi][nf][3] *= c1;
            }

            // PV: f16 P x f16 V (V frags re-read per mi; 2x amortized overall)
#pragma unroll
            for (int j = 0; j < 4; j++) {
#pragma unroll
                for (int t = 0; t < 4; t++) {
                    uint32_t vf[4];
                    LDSM4T(vf, Vf_ + swz(j * 2048 + vOffBase + t * 32));
                    MMA_F16(o_[mi][2 * t],     ph[j], vf[0], vf[1]);
                    MMA_F16(o_[mi][2 * t + 1], ph[j], vf[2], vf[3]);
                }
            }
        }
    }

    // ---- epilogue ----
#pragma unroll
    for (int mi = 0; mi < 2; mi++) {
        const int rA = (mi == 0) ? rA0 : rA1;
        const float iA = 1.0f / lrow[mi][0];
        const float iB = 1.0f / lrow[mi][1];
        const size_t rowA = (size_t)(b * SEQ + rA) * EMB + h * 64;
        const size_t rowB = (size_t)(b * SEQ + rA + 8) * EMB + h * 64;
#pragma unroll
        for (int nf = 0; nf < 8; nf++) {
            const int d = nf * 8 + (lane & 3) * 2;
            *(uint32_t*)&g_Of[rowA + d] = packh2(o_[mi][nf][0] * iA, o_[mi][nf][1] * iA);
            *(uint32_t*)&g_Of[rowB + d] = packh2(o_[mi][nf][2] * iB, o_[mi][nf][3] * iB);
        }
    }
}

// ---------------------------------------------------------------------------
extern "C" void kernel_launch(void* const* d_in, const int* in_sizes, int n_in,
                              void* d_out, int out_size)
{
    const float* x  = (const float*)d_in[0];
    const float* Wq = (const float*)d_in[1];
    const float* Wk = (const float*)d_in[2];
    const float* Wv = (const float*)d_in[3];
    const float* Wo = (const float*)d_in[4];
    float* out = (float*)d_out;

    cudaFuncSetAttribute(proj_all,
                         cudaFuncAttributeMaxDynamicSharedMemorySize, PROJ_SMEM);
    cudaFuncSetAttribute(gemm_o,
                         cudaFuncAttributeMaxDynamicSharedMemorySize, GO_SMEM);
    cudaFuncSetAttribute(flash_mma,
                         cudaFuncAttributeMaxDynamicSharedMemorySize, FL_SMEM);

    // Convert X (bf16 hi/lo + f16) and W (Wq/Wk bf16 hi/lo, Wv/Wo f16)
    convert_all<<<2560, 256>>>(x, Wq, Wk, Wv, Wo);

    // Q,K (bf16x3) + V (f16) projections, conflict-free SW128 smem
    proj_all<<<768, 256, PROJ_SMEM>>>();

    // Flash attention (256-q-row CTAs, halved K/V crossbar traffic) -> Of
    flash_mma<<<dim3(SEQ/256, NH, BATCH), 256, FL_SMEM>>>();

    // Output projection (single f16) -> fp32 out
    gemm_o<<<dim3(8, 32), 256, GO_SMEM>>>(out);
}

// round 15
// speedup vs baseline: 1.0644x; 1.0644x over previous
#include <cuda_runtime.h>
#include <cuda_bf16.h>
#include <cuda_fp16.h>
#include <math.h>
#include <stdint.h>

#define BATCH 2
#define SEQ   2048
#define EMB   1024
#define NH    16
#define DH    64
#define M_TOT (BATCH*SEQ)   // 4096

// ---------------------------------------------------------------------------
// Device scratch
// ---------------------------------------------------------------------------
__device__ __nv_bfloat16 g_Xhi[M_TOT*EMB];
__device__ __nv_bfloat16 g_Xlo[M_TOT*EMB];
__device__ __half        g_Xf[M_TOT*EMB];
__device__ __nv_bfloat16 g_Whi[2*EMB*EMB];   // Wq, Wk (bf16 hi)
__device__ __nv_bfloat16 g_Wlo[2*EMB*EMB];   // Wq, Wk (bf16 lo)
__device__ __half        g_Wf[2*EMB*EMB];    // Wv, Wo (single f16)
__device__ __nv_bfloat16 g_Qhi[BATCH*NH*SEQ*DH];
__device__ __nv_bfloat16 g_Qlo[BATCH*NH*SEQ*DH];
__device__ __nv_bfloat16 g_Khi[BATCH*NH*SEQ*DH];
__device__ __nv_bfloat16 g_Klo[BATCH*NH*SEQ*DH];
__device__ __half        g_Vf[BATCH*NH*SEQ*DH];   // head-major, single f16
__device__ __half        g_Of[M_TOT*EMB];         // row-major, single f16

// ---------------------------------------------------------------------------
// PTX helpers (portable sm_80-class only)
// ---------------------------------------------------------------------------
__device__ __forceinline__ uint32_t smem_u32(const void* p) {
    uint32_t a;
    asm("{ .reg .u64 t; cvta.to.shared.u64 t, %1; cvt.u32.u64 %0, t; }" : "=r"(a) : "l"(p));
    return a;
}

#define CP_ASYNC16(dst, src) \
    asm volatile("cp.async.cg.shared.global [%0], [%1], 16;" :: "r"(dst), "l"(src))
#define CP_COMMIT() asm volatile("cp.async.commit_group;")
#define CP_WAIT0()  asm volatile("cp.async.wait_group 0;")
#define CP_WAIT1()  asm volatile("cp.async.wait_group 1;")

#define LDSM4(r, addr) \
    asm volatile("ldmatrix.sync.aligned.m8n8.x4.shared.b16 {%0,%1,%2,%3}, [%4];" \
        : "=r"((r)[0]), "=r"((r)[1]), "=r"((r)[2]), "=r"((r)[3]) : "r"(addr))
#define LDSM4T(r, addr) \
    asm volatile("ldmatrix.sync.aligned.m8n8.x4.trans.shared.b16 {%0,%1,%2,%3}, [%4];" \
        : "=r"((r)[0]), "=r"((r)[1]), "=r"((r)[2]), "=r"((r)[3]) : "r"(addr))

#define MMA_BF16(c, a, b0v, b1v) \
    asm volatile("mma.sync.aligned.m16n8k16.row.col.f32.bf16.bf16.f32 " \
        "{%0,%1,%2,%3}, {%4,%5,%6,%7}, {%8,%9}, {%0,%1,%2,%3};" \
        : "+f"((c)[0]), "+f"((c)[1]), "+f"((c)[2]), "+f"((c)[3]) \
        : "r"((a)[0]), "r"((a)[1]), "r"((a)[2]), "r"((a)[3]), "r"(b0v), "r"(b1v))

#define MMA_F16(c, a, b0v, b1v) \
    asm volatile("mma.sync.aligned.m16n8k16.row.col.f32.f16.f16.f32 " \
        "{%0,%1,%2,%3}, {%4,%5,%6,%7}, {%8,%9}, {%0,%1,%2,%3};" \
        : "+f"((c)[0]), "+f"((c)[1]), "+f"((c)[2]), "+f"((c)[3]) \
        : "r"((a)[0]), "r"((a)[1]), "r"((a)[2]), "r"((a)[3]), "r"(b0v), "r"(b1v))

__device__ __forceinline__ float fast_exp2(float x) {
    float r;
    asm("ex2.approx.ftz.f32 %0, %1;" : "=f"(r) : "f"(x));
    return r;
}

__device__ __forceinline__ uint32_t packbf2(float lo, float hi) {
    uint32_t r;
    asm("cvt.rn.bf16x2.f32 %0, %1, %2;" : "=r"(r) : "f"(hi), "f"(lo));
    return r;
}
__device__ __forceinline__ float bflo(uint32_t u) { return __uint_as_float(u << 16); }
__device__ __forceinline__ float bfhi(uint32_t u) { return __uint_as_float(u & 0xFFFF0000u); }

__device__ __forceinline__ uint32_t packh2(float a, float b) {
    __half2 h = __floats2half2_rn(a, b);
    return *(uint32_t*)&h;
}
__device__ __forceinline__ float hsum2(uint32_t u) {
    __half2 h = *(__half2*)&u;
    float2 f = __half22float2(h);
    return f.x + f.y;
}

__device__ __forceinline__ uint32_t swz(uint32_t off) {   // SW128 for 128B rows
    return off ^ ((off >> 3) & 0x70);
}
__device__ __forceinline__ uint32_t swz64(uint32_t off) { // SW64 for 64B rows
    return off ^ ((off >> 2) & 0x30);
}

// ---------------------------------------------------------------------------
// Fused conversion kernel: blocks [0,2048) convert X; [2048,2560) convert W.
// ---------------------------------------------------------------------------
__global__ void convert_all(const float* __restrict__ X,
                            const float* __restrict__ W0, const float* __restrict__ W1,
                            const float* __restrict__ W2, const float* __restrict__ W3)
{
    __shared__ float Wsm[64][129];
    const int tid = threadIdx.x;
    if (blockIdx.x < 2048) {
        int gid = blockIdx.x * 256 + tid;
        size_t base = (size_t)gid * 8;
        float4 v0 = *(const float4*)&X[base];
        float4 v1 = *(const float4*)&X[base + 4];
        float vs[8] = {v0.x, v0.y, v0.z, v0.w, v1.x, v1.y, v1.z, v1.w};
        __nv_bfloat16 h[8], l[8];
        __half f[8];
#pragma unroll
        for (int i = 0; i < 8; i++) {
            h[i] = __float2bfloat16(vs[i]);
            l[i] = __float2bfloat16(vs[i] - __bfloat162float(h[i]));
            f[i] = __float2half_rn(vs[i]);
        }
        *(uint4*)&g_Xhi[base] = *(uint4*)h;
        *(uint4*)&g_Xlo[base] = *(uint4*)l;
        *(uint4*)&g_Xf[base]  = *(uint4*)f;
        return;
    }

    int bi = blockIdx.x - 2048;
    int w = bi >> 7;
    int rest = bi & 127;
    int ntile = rest >> 4;
    int kc = rest & 15;
    const float* W = (w == 0) ? W0 : (w == 1) ? W1 : (w == 2) ? W2 : W3;

#pragma unroll
    for (int i = 0; i < 32; i++) {
        int lin = i * 256 + tid;
        int kr = lin >> 7;
        int nc = lin & 127;
        Wsm[kr][nc] = W[(size_t)(kc * 64 + kr) * EMB + ntile * 128 + nc];
    }
    __syncthreads();

#pragma unroll
    for (int j = 0; j < 4; j++) {
        int lin = j * 256 + tid;
        int nin = lin >> 3;
        int g = lin & 7;
        float vs[8];
#pragma unroll
        for (int i = 0; i < 8; i++) vs[i] = Wsm[g * 8 + i][nin];
        if (w < 2) {
            size_t base = ((size_t)(w * EMB + ntile * 128 + nin)) * EMB + kc * 64 + g * 8;
            __nv_bfloat16 h[8], l[8];
#pragma unroll
            for (int i = 0; i < 8; i++) {
                h[i] = __float2bfloat16(vs[i]);
                l[i] = __float2bfloat16(vs[i] - __bfloat162float(h[i]));
            }
            *(uint4*)&g_Whi[base] = *(uint4*)h;
            *(uint4*)&g_Wlo[base] = *(uint4*)l;
        } else {
            size_t base = ((size_t)((w - 2) * EMB + ntile * 128 + nin)) * EMB + kc * 64 + g * 8;
            __half h[8];
#pragma unroll
            for (int i = 0; i < 8; i++) h[i] = __float2half_rn(vs[i]);
            *(uint4*)&g_Wf[base] = *(uint4*)h;
        }
    }
}

// ---------------------------------------------------------------------------
// Merged QKV projection v2: 768 CTAs, 256 thr, CTA tile 128x128, BK=32,
// 64B SW64-swizzled smem rows. Stage = 32KB (QK), 3 stages = 96KB
// -> 2 CTAs/SM (sync bubbles of one CTA hidden by the other).
//   CTA [0,512):   bf16x3 (Q: z=0, K: z=1)
//   CTA [512,768): single-f16 V
// Same FP accumulation order as r12 (ascending k16; hh->hl->lh per acc).
// ---------------------------------------------------------------------------
#define PT32 8192                        // 128 rows * 64B
#define PSTG_QK (4*PT32)                 // 32768
#define PSTG_V  (2*PT32)                 // 16384
#define PROJ_SMEM (3*PSTG_QK)            // 98304

__global__ __launch_bounds__(256, 2)
void proj_all()
{
    extern __shared__ __align__(128) char smem[];
    const uint32_t sb = smem_u32(smem);
    const int tid = threadIdx.x, lane = tid & 31, wid = tid >> 5;
    const int wm = wid & 3, wn = wid >> 2;        // 4m x 2n

    const uint32_t aBase = (wm * 32 + (lane & 15)) * 64 + (lane >> 4) * 16;
    const uint32_t bBase = (wn * 64 + (lane & 7) + ((lane >> 4) << 3)) * 64
                         + ((lane >> 3) & 1) * 16;
    const int lrow = tid >> 2;          // 0..63
    const int lseg = tid & 3;           // 16B segment in 64B row

    float acc[2][8][4];
#pragma unroll
    for (int i = 0; i < 2; i++)
#pragma unroll
        for (int j = 0; j < 8; j++)
#pragma unroll
            for (int q = 0; q < 4; q++) acc[i][j][q] = 0.0f;

    if (blockIdx.x < 512) {
        // ---------------- Q/K bf16x3 path ----------------
        const int z = blockIdx.x >> 8;
        const int r = blockIdx.x & 255;
        const int bx = r & 7, by = r >> 3;

        const __nv_bfloat16* Bhi = g_Whi + (size_t)z * EMB * EMB;
        const __nv_bfloat16* Blo = g_Wlo + (size_t)z * EMB * EMB;

        auto load_stage = [&](int c, int slot) {
            const int k0 = c * 32;
            const uint32_t st = sb + slot * PSTG_QK;
#pragma unroll
            for (int i = 0; i < 2; i++) {
                const int rr = i * 64 + lrow;
                const uint32_t d = swz64(rr * 64 + lseg * 16);
                const size_t gi = (size_t)(by * 128 + rr) * EMB + k0 + lseg * 8;
                const size_t gw = (size_t)(bx * 128 + rr) * EMB + k0 + lseg * 8;
                CP_ASYNC16(st + d,            g_Xhi + gi);
                CP_ASYNC16(st + PT32 + d,     g_Xlo + gi);
                CP_ASYNC16(st + 2*PT32 + d,   Bhi + gw);
                CP_ASYNC16(st + 3*PT32 + d,   Blo + gw);
            }
            CP_COMMIT();
        };

        load_stage(0, 0);
        load_stage(1, 1);

        for (int c = 0; c < 32; c++) {
            CP_WAIT1();
            __syncthreads();
            if (c + 2 < 32) load_stage(c + 2, (c + 2) % 3);
            const uint32_t st = sb + (c % 3) * PSTG_QK;
            const uint32_t Ah = st, Al = st + PT32;
            const uint32_t Bh = st + 2*PT32, Bl = st + 3*PT32;

#pragma unroll
            for (int kc = 0; kc < 2; kc++) {
                const uint32_t kB = kc * 32;
                uint32_t ar[2][4], bh[4][4], bt[4][4];
                // bh + ah resident
#pragma unroll
                for (int ni = 0; ni < 4; ni++)
                    LDSM4(bh[ni], Bh + swz64(bBase + ni * 1024 + kB));
#pragma unroll
                for (int mi = 0; mi < 2; mi++)
                    LDSM4(ar[mi], Ah + swz64(aBase + mi * 1024 + kB));
                // hh pass
#pragma unroll
                for (int mi = 0; mi < 2; mi++)
#pragma unroll
                    for (int ni = 0; ni < 4; ni++) {
                        MMA_BF16(acc[mi][2*ni],   ar[mi], bh[ni][0], bh[ni][1]);
                        MMA_BF16(acc[mi][2*ni+1], ar[mi], bh[ni][2], bh[ni][3]);
                    }
                // hl pass (bl transient in bt)
#pragma unroll
                for (int ni = 0; ni < 4; ni++)
                    LDSM4(bt[ni], Bl + swz64(bBase + ni * 1024 + kB));
#pragma unroll
                for (int mi = 0; mi < 2; mi++)
#pragma unroll
                    for (int ni = 0; ni < 4; ni++) {
                        MMA_BF16(acc[mi][2*ni],   ar[mi], bt[ni][0], bt[ni][1]);
                        MMA_BF16(acc[mi][2*ni+1], ar[mi], bt[ni][2], bt[ni][3]);
                    }
                // lh pass (al overwrites ar)
#pragma unroll
                for (int mi = 0; mi < 2; mi++)
                    LDSM4(ar[mi], Al + swz64(aBase + mi * 1024 + kB));
#pragma unroll
                for (int mi = 0; mi < 2; mi++)
#pragma unroll
                    for (int ni = 0; ni < 4; ni++) {
                        MMA_BF16(acc[mi][2*ni],   ar[mi], bh[ni][0], bh[ni][1]);
                        MMA_BF16(acc[mi][2*ni+1], ar[mi], bh[ni][2], bh[ni][3]);
                    }
            }
        }
        __syncthreads();

        float* Cs = (float*)smem;            // [128][132] = 67584B < 98304
#pragma unroll
        for (int mi = 0; mi < 2; mi++)
#pragma unroll
            for (int nf = 0; nf < 8; nf++) {
                const int r0 = wm * 32 + mi * 16 + (lane >> 2);
                const int col = wn * 64 + nf * 8 + (lane & 3) * 2;
                *(float2*)&Cs[r0 * 132 + col]       = make_float2(acc[mi][nf][0], acc[mi][nf][1]);
                *(float2*)&Cs[(r0 + 8) * 132 + col] = make_float2(acc[mi][nf][2], acc[mi][nf][3]);
            }
        __syncthreads();

#pragma unroll
        for (int it = 0; it < 16; it++) {
            const int lin = it * 256 + tid;
            const int rr = lin >> 5;
            const int cg = (lin & 31) * 4;
            float4 v = *(const float4*)&Cs[rr * 132 + cg];
            const int m = by * 128 + rr;
            const int n = bx * 128 + cg;
            const int b = m >> 11, s = m & 2047, h = n >> 6, d = n & 63;
            __nv_bfloat16* dh = (z == 0) ? g_Qhi : g_Khi;
            __nv_bfloat16* dl = (z == 0) ? g_Qlo : g_Klo;
            uint32_t u0 = packbf2(v.x, v.y), u1 = packbf2(v.z, v.w);
            uint32_t l0 = packbf2(v.x - bflo(u0), v.y - bfhi(u0));
            uint32_t l1 = packbf2(v.z - bflo(u1), v.w - bfhi(u1));
            size_t addr = (((size_t)(b * NH + h)) * SEQ + s) * DH + d;
            *(uint2*)&dh[addr] = make_uint2(u0, u1);
            *(uint2*)&dl[addr] = make_uint2(l0, l1);
        }
    } else {
        // ---------------- V single-f16 path ----------------
        const int j = blockIdx.x - 512;
        const int bx = j & 7, by = j >> 3;
        const __half* Bf = g_Wf;

        auto load_stage = [&](int c, int slot) {
            const int k0 = c * 32;
            const uint32_t st = sb + slot * PSTG_V;
#pragma unroll
            for (int i = 0; i < 2; i++) {
                const int rr = i * 64 + lrow;
                const uint32_t d = swz64(rr * 64 + lseg * 16);
                CP_ASYNC16(st + d,
                           g_Xf + (size_t)(by * 128 + rr) * EMB + k0 + lseg * 8);
                CP_ASYNC16(st + PT32 + d,
                           Bf + (size_t)(bx * 128 + rr) * EMB + k0 + lseg * 8);
            }
            CP_COMMIT();
        };

        load_stage(0, 0);
        load_stage(1, 1);

        for (int c = 0; c < 32; c++) {
            CP_WAIT1();
            __syncthreads();
            if (c + 2 < 32) load_stage(c + 2, (c + 2) % 3);
            const uint32_t st = sb + (c % 3) * PSTG_V;
            const uint32_t At = st, Bt = st + PT32;

#pragma unroll
            for (int kc = 0; kc < 2; kc++) {
                const uint32_t kB = kc * 32;
                uint32_t ar[2][4], bh[4][4];
#pragma unroll
                for (int ni = 0; ni < 4; ni++)
                    LDSM4(bh[ni], Bt + swz64(bBase + ni * 1024 + kB));
#pragma unroll
                for (int mi = 0; mi < 2; mi++)
                    LDSM4(ar[mi], At + swz64(aBase + mi * 1024 + kB));
#pragma unroll
                for (int mi = 0; mi < 2; mi++)
#pragma unroll
                    for (int ni = 0; ni < 4; ni++) {
                        MMA_F16(acc[mi][2*ni],   ar[mi], bh[ni][0], bh[ni][1]);
                        MMA_F16(acc[mi][2*ni+1], ar[mi], bh[ni][2], bh[ni][3]);
                    }
            }
        }
        __syncthreads();

        float* Cs = (float*)smem;
#pragma unroll
        for (int mi = 0; mi < 2; mi++)
#pragma unroll
            for (int nf = 0; nf < 8; nf++) {
                const int r0 = wm * 32 + mi * 16 + (lane >> 2);
                const int col = wn * 64 + nf * 8 + (lane & 3) * 2;
                *(float2*)&Cs[r0 * 132 + col]       = make_float2(acc[mi][nf][0], acc[mi][nf][1]);
                *(float2*)&Cs[(r0 + 8) * 132 + col] = make_float2(acc[mi][nf][2], acc[mi][nf][3]);
            }
        __syncthreads();

#pragma unroll
        for (int it = 0; it < 16; it++) {
            const int lin = it * 256 + tid;
            const int rr = lin >> 5;
            const int cg = (lin & 31) * 4;
            float4 v = *(const float4*)&Cs[rr * 132 + cg];
            const int m = by * 128 + rr;
            const int n = bx * 128 + cg;
            const int b = m >> 11, s = m & 2047, h = n >> 6, d = n & 63;
            size_t addr = (((size_t)(b * NH + h)) * SEQ + s) * DH + d;
            *(uint2*)&g_Vf[addr] = make_uint2(packh2(v.x, v.y), packh2(v.z, v.w));
        }
    }
}

// ---------------------------------------------------------------------------
// gemm_o: single-f16 GEMM (r12 — frozen).
// ---------------------------------------------------------------------------
#define PA_TILE 16384                    // 128 rows * 128B
#define GO_STAGE (2*PA_TILE)             // 32768
#define GO_SMEM  (3*GO_STAGE)            // 98304

__global__ __launch_bounds__(256, 2)
void gemm_o(float* __restrict__ Cout)
{
    extern __shared__ __align__(128) char smem[];
    const uint32_t sb = smem_u32(smem);
    const int tid = threadIdx.x, lane = tid & 31, wid = tid >> 5;
    const int wm = wid & 3, wn = wid >> 2;
    const int bx = blockIdx.x, by = blockIdx.y;

    const __half* Bf = g_Wf + (size_t)EMB * EMB;   // Wo

    const uint32_t aBase = (wm * 32 + (lane & 15)) * 128 + (lane >> 4) * 16;
    const uint32_t bBase = (wn * 64 + (lane & 7) + ((lane >> 4) << 3)) * 128
                         + ((lane >> 3) & 1) * 16;
    const int lrow = tid >> 3;
    const int lseg = tid & 7;

    float acc[2][8][4];
#pragma unroll
    for (int i = 0; i < 2; i++)
#pragma unroll
        for (int j = 0; j < 8; j++)
#pragma unroll
            for (int q = 0; q < 4; q++) acc[i][j][q] = 0.0f;

    auto load_stage = [&](int c, int slot) {
        const int k0 = c * 64;
        const uint32_t st = sb + slot * GO_STAGE;
#pragma unroll
        for (int i = 0; i < 4; i++) {
            const int rr = i * 32 + lrow;
            const uint32_t d = swz(rr * 128 + lseg * 16);
            CP_ASYNC16(st + d,
                       g_Of + (size_t)(by * 128 + rr) * EMB + k0 + lseg * 8);
            CP_ASYNC16(st + PA_TILE + d,
                       Bf + (size_t)(bx * 128 + rr) * EMB + k0 + lseg * 8);
        }
        CP_COMMIT();
    };

    load_stage(0, 0);
    load_stage(1, 1);

    for (int c = 0; c < 16; c++) {
        CP_WAIT1();
        __syncthreads();
        if (c + 2 < 16) load_stage(c + 2, (c + 2) % 3);
        const uint32_t st = sb + (c % 3) * GO_STAGE;
        const uint32_t At = st, Bt = st + PA_TILE;

#pragma unroll
        for (int kc = 0; kc < 4; kc++) {
            const uint32_t kB = kc * 32;
            uint32_t ar[2][4], bh[4][4];
#pragma unroll
            for (int ni = 0; ni < 4; ni++)
                LDSM4(bh[ni], Bt + swz(bBase + ni * 2048 + kB));
#pragma unroll
            for (int mi = 0; mi < 2; mi++)
                LDSM4(ar[mi], At + swz(aBase + mi * 2048 + kB));
#pragma unroll
            for (int mi = 0; mi < 2; mi++)
#pragma unroll
                for (int ni = 0; ni < 4; ni++) {
                    MMA_F16(acc[mi][2*ni],   ar[mi], bh[ni][0], bh[ni][1]);
                    MMA_F16(acc[mi][2*ni+1], ar[mi], bh[ni][2], bh[ni][3]);
                }
        }
    }
    __syncthreads();

    float* Cs = (float*)smem;            // [128][132]
#pragma unroll
    for (int mi = 0; mi < 2; mi++)
#pragma unroll
        for (int nf = 0; nf < 8; nf++) {
            const int r0 = wm * 32 + mi * 16 + (lane >> 2);
            const int col = wn * 64 + nf * 8 + (lane & 3) * 2;
            *(float2*)&Cs[r0 * 132 + col]       = make_float2(acc[mi][nf][0], acc[mi][nf][1]);
            *(float2*)&Cs[(r0 + 8) * 132 + col] = make_float2(acc[mi][nf][2], acc[mi][nf][3]);
        }
    __syncthreads();

#pragma unroll
    for (int it = 0; it < 16; it++) {
        const int lin = it * 256 + tid;
        const int rr = lin >> 5;
        const int cg = (lin & 31) * 4;
        float4 v = *(const float4*)&Cs[rr * 132 + cg];
        const int m = by * 128 + rr;
        const int n = bx * 128 + cg;
        *(float4*)&Cout[(size_t)m * EMB + n] = v;
    }
}

// ---------------------------------------------------------------------------
// Flash attention (r12 — frozen, best known): 128 q-rows, 128-row KV tiles,
// QK bf16x3, PV f16 P x f16 V (l over rounded P).
// ---------------------------------------------------------------------------
#define KV_STAGE 49152      // Kh 16KB + Kl 16KB + Vf 16KB
#define FL_SMEM (32768 + 2*KV_STAGE)   // 131072
#define CEXP 0.18033688f    // 0.125 * log2(e)

__global__ __launch_bounds__(256, 1)
void flash_mma()
{
    const int qi = (int)gridDim.x - 1 - blockIdx.x;   // heavy tiles first
    const int h = blockIdx.y, b = blockIdx.z;
    const int tid = threadIdx.x, lane = tid & 31, w = tid >> 5;
    extern __shared__ __align__(128) char smf[];
    const uint32_t sb = smem_u32(smf);
    const uint32_t Qh_ = sb, Ql_ = sb + 16384;

    const size_t head = ((size_t)(b * NH + h)) * SEQ * DH;
    const __nv_bfloat16* Qhg = g_Qhi + head;
    const __nv_bfloat16* Qlg = g_Qlo + head;
    const __nv_bfloat16* Khg = g_Khi + head;
    const __nv_bfloat16* Klg = g_Klo + head;
    const __half*        Vfg = g_Vf  + head;
    const int qbase = qi * 128;

#pragma unroll
    for (int i = 0; i < 4; i++) {
        int lin = i * 256 + tid;
        int r = lin >> 3, c = lin & 7;
        uint32_t off = swz(r * 128 + c * 16);
        CP_ASYNC16(Qh_ + off, Qhg + (size_t)(qbase + r) * 64 + c * 8);
        CP_ASYNC16(Ql_ + off, Qlg + (size_t)(qbase + r) * 64 + c * 8);
    }
    CP_COMMIT();

    auto load_kv = [&](int jt, int slot) {
        const uint32_t st = sb + 32768 + slot * KV_STAGE;
#pragma unroll
        for (int i = 0; i < 4; i++) {
            int lin = i * 256 + tid;
            int r = lin >> 3, c = lin & 7;
            uint32_t off = swz(r * 128 + c * 16);
            size_t gidx = (size_t)(jt * 128 + r) * 64 + c * 8;
            CP_ASYNC16(st + off,             Khg + gidx);
            CP_ASYNC16(st + 16384 + off,     Klg + gidx);
            CP_ASYNC16(st + 32768 + off,     Vfg + gidx);
        }
        CP_COMMIT();
    };

    load_kv(0, 0);
    CP_WAIT1();
    __syncthreads();

    uint32_t qh[4][4], ql[4][4];
    const uint32_t qoff = (w * 16 + (lane & 15)) * 128 + (lane >> 4) * 16;
#pragma unroll
    for (int kc = 0; kc < 4; kc++) {
        LDSM4(qh[kc], Qh_ + swz(qoff + kc * 32));
        LDSM4(ql[kc], Ql_ + swz(qoff + kc * 32));
    }

    float o_[8][4];
#pragma unroll
    for (int i = 0; i < 8; i++)
#pragma unroll
        for (int j = 0; j < 4; j++) o_[i][j] = 0.0f;
    float mrow[2] = {-3e38f, -3e38f};
    float lrow[2] = {0.0f, 0.0f};

    const int rA = qbase + w * 16 + (lane >> 2);
    const int rB = rA + 8;
    const uint32_t kOffBase = ((lane & 7) + ((lane >> 4) << 3)) * 128 + ((lane >> 3) & 1) * 16;
    const uint32_t vOffBase = (lane & 15) * 128 + (lane >> 4) * 16;

    for (int jt = 0; jt <= qi; jt++) {
        CP_WAIT0();
        __syncthreads();
        if (jt < qi) load_kv(jt + 1, (jt + 1) & 1);
        const uint32_t st = sb + 32768 + (jt & 1) * KV_STAGE;
        const uint32_t Kh_ = st, Kl_ = st + 16384, Vf_ = st + 32768;

        float s_[16][4];
#pragma unroll
        for (int i = 0; i < 16; i++)
#pragma unroll
            for (int j = 0; j < 4; j++) s_[i][j] = 0.0f;

#pragma unroll
        for (int tp = 0; tp < 4; tp++) {
#pragma unroll
            for (int kc = 0; kc < 4; kc++) {
                const uint32_t addrA = swz((2*tp)   * 16 * 128 + kOffBase + kc * 32);
                const uint32_t addrB = swz((2*tp+1) * 16 * 128 + kOffBase + kc * 32);
                uint32_t bha[4], bla[4], bhb[4], blb[4];
                LDSM4(bha, Kh_ + addrA);
                LDSM4(bhb, Kh_ + addrB);
                LDSM4(bla, Kl_ + addrA);
                LDSM4(blb, Kl_ + addrB);
                MMA_BF16(s_[4*tp],     qh[kc], bha[0], bha[1]);
                MMA_BF16(s_[4*tp + 1], qh[kc], bha[2], bha[3]);
                MMA_BF16(s_[4*tp + 2], qh[kc], bhb[0], bhb[1]);
                MMA_BF16(s_[4*tp + 3], qh[kc], bhb[2], bhb[3]);
                MMA_BF16(s_[4*tp],     ql[kc], bha[0], bha[1]);
                MMA_BF16(s_[4*tp + 1], ql[kc], bha[2], bha[3]);
                MMA_BF16(s_[4*tp + 2], ql[kc], bhb[0], bhb[1]);
                MMA_BF16(s_[4*tp + 3], ql[kc], bhb[2], bhb[3]);
                MMA_BF16(s_[4*tp],     qh[kc], bla[0], bla[1]);
                MMA_BF16(s_[4*tp + 1], qh[kc], bla[2], bla[3]);
                MMA_BF16(s_[4*tp + 2], qh[kc], blb[0], blb[1]);
                MMA_BF16(s_[4*tp + 3], qh[kc], blb[2], blb[3]);
            }
        }

        if (jt == qi) {
#pragma unroll
            for (int nf = 0; nf < 16; nf++) {
                const int colg = jt * 128 + nf * 8 + (lane & 3) * 2;
                if (colg     > rA) s_[nf][0] = -3e38f;
                if (colg + 1 > rA) s_[nf][1] = -3e38f;
                if (colg     > rB) s_[nf][2] = -3e38f;
                if (colg + 1 > rB) s_[nf][3] = -3e38f;
            }
        }

        float mx0 = -3e38f, mx1 = -3e38f;
#pragma unroll
        for (int nf = 0; nf < 16; nf++) {
            mx0 = fmaxf(mx0, fmaxf(s_[nf][0], s_[nf][1]));
            mx1 = fmaxf(mx1, fmaxf(s_[nf][2], s_[nf][3]));
        }
        mx0 = fmaxf(mx0, __shfl_xor_sync(0xffffffffu, mx0, 1));
        mx0 = fmaxf(mx0, __shfl_xor_sync(0xffffffffu, mx0, 2));
        mx1 = fmaxf(mx1, __shfl_xor_sync(0xffffffffu, mx1, 1));
        mx1 = fmaxf(mx1, __shfl_xor_sync(0xffffffffu, mx1, 2));
        const float mn0 = fmaxf(mrow[0], mx0);
        const float mn1 = fmaxf(mrow[1], mx1);
        const float c0 = fast_exp2((mrow[0] - mn0) * CEXP);
        const float c1 = fast_exp2((mrow[1] - mn1) * CEXP);
        mrow[0] = mn0; mrow[1] = mn1;

        uint32_t ph[8][4];
        float rs0 = 0.0f, rs1 = 0.0f;
#pragma unroll
        for (int j = 0; j < 8; j++) {
            const float p00 = fast_exp2((s_[2*j][0]   - mn0) * CEXP);
            const float p01 = fast_exp2((s_[2*j][1]   - mn0) * CEXP);
            const float p10 = fast_exp2((s_[2*j][2]   - mn1) * CEXP);
            const float p11 = fast_exp2((s_[2*j][3]   - mn1) * CEXP);
            const float p20 = fast_exp2((s_[2*j+1][0] - mn0) * CEXP);
            const float p21 = fast_exp2((s_[2*j+1][1] - mn0) * CEXP);
            const float p30 = fast_exp2((s_[2*j+1][2] - mn1) * CEXP);
            const float p31 = fast_exp2((s_[2*j+1][3] - mn1) * CEXP);
            ph[j][0] = packh2(p00, p01);
            ph[j][1] = packh2(p10, p11);
            ph[j][2] = packh2(p20, p21);
            ph[j][3] = packh2(p30, p31);
            rs0 += hsum2(ph[j][0]) + hsum2(ph[j][2]);
            rs1 += hsum2(ph[j][1]) + hsum2(ph[j][3]);
        }
        rs0 += __shfl_xor_sync(0xffffffffu, rs0, 1);
        rs0 += __shfl_xor_sync(0xffffffffu, rs0, 2);
        rs1 += __shfl_xor_sync(0xffffffffu, rs1, 1);
        rs1 += __shfl_xor_sync(0xffffffffu, rs1, 2);
        lrow[0] = lrow[0] * c0 + rs0;
        lrow[1] = lrow[1] * c1 + rs1;
#pragma unroll
        for (int nf = 0; nf < 8; nf++) {
            o_[nf][0] *= c0; o_[nf][1] *= c0;
            o_[nf][2] *= c1; o_[nf][3] *= c1;
        }

#pragma unroll
        for (int j = 0; j < 8; j++) {
#pragma unroll
            for (int t = 0; t < 4; t++) {
                uint32_t vf[4];
                LDSM4T(vf, Vf_ + swz(j * 16 * 128 + vOffBase + t * 32));
                MMA_F16(o_[2 * t],     ph[j], vf[0], vf[1]);
                MMA_F16(o_[2 * t + 1], ph[j], vf[2], vf[3]);
            }
        }
    }

    const float iA = 1.0f / lrow[0];
    const float iB = 1.0f / lrow[1];
    const size_t rowA = (size_t)(b * SEQ + rA) * EMB + h * 64;
    const size_t rowB = (size_t)(b * SEQ + rB) * EMB + h * 64;
#pragma unroll
    for (int nf = 0; nf < 8; nf++) {
        const int d = nf * 8 + (lane & 3) * 2;
        *(uint32_t*)&g_Of[rowA + d] = packh2(o_[nf][0] * iA, o_[nf][1] * iA);
        *(uint32_t*)&g_Of[rowB + d] = packh2(o_[nf][2] * iB, o_[nf][3] * iB);
    }
}

// ---------------------------------------------------------------------------
extern "C" void kernel_launch(void* const* d_in, const int* in_sizes, int n_in,
                              void* d_out, int out_size)
{
    const float* x  = (const float*)d_in[0];
    const float* Wq = (const float*)d_in[1];
    const float* Wk = (const float*)d_in[2];
    const float* Wv = (const float*)d_in[3];
    const float* Wo = (const float*)d_in[4];
    float* out = (float*)d_out;

    cudaFuncSetAttribute(proj_all,
                         cudaFuncAttributeMaxDynamicSharedMemorySize, PROJ_SMEM);
    cudaFuncSetAttribute(gemm_o,
                         cudaFuncAttributeMaxDynamicSharedMemorySize, GO_SMEM);
    cudaFuncSetAttribute(flash_mma,
                         cudaFuncAttributeMaxDynamicSharedMemorySize, FL_SMEM);

    // Convert X (bf16 hi/lo + f16) and W (Wq/Wk bf16 hi/lo, Wv/Wo f16)
    convert_all<<<2560, 256>>>(x, Wq, Wk, Wv, Wo);

    // Q,K (bf16x3) + V (f16) projections, BK=32 SW64, 2 CTAs/SM
    proj_all<<<768, 256, PROJ_SMEM>>>();

    // Flash attention (r12 frozen) -> Of
    flash_mma<<<dim3(SEQ/128, NH, BATCH), 256, FL_SMEM>>>();

    // Output projection (single f16) -> fp32 out
    gemm_o<<<dim3(8, 32), 256, GO_SMEM>>>(out);
}

// round 16
// speedup vs baseline: 1.1056x; 1.0387x over previous
#include <cuda_runtime.h>
#include <cuda_bf16.h>
#include <cuda_fp16.h>
#include <math.h>
#include <stdint.h>

#define BATCH 2
#define SEQ   2048
#define EMB   1024
#define NH    16
#define DH    64
#define M_TOT (BATCH*SEQ)   // 4096

// ---------------------------------------------------------------------------
// Device scratch
// ---------------------------------------------------------------------------
__device__ __nv_bfloat16 g_Xhi[M_TOT*EMB];
__device__ __nv_bfloat16 g_Xlo[M_TOT*EMB];
__device__ __half        g_Xf[M_TOT*EMB];
__device__ __nv_bfloat16 g_Whi[2*EMB*EMB];   // Wq, Wk (bf16 hi)
__device__ __nv_bfloat16 g_Wlo[2*EMB*EMB];   // Wq, Wk (bf16 lo)
__device__ __half        g_Wf[2*EMB*EMB];    // Wv, Wo (single f16)
__device__ __nv_bfloat16 g_Qhi[BATCH*NH*SEQ*DH];
__device__ __nv_bfloat16 g_Qlo[BATCH*NH*SEQ*DH];
__device__ __nv_bfloat16 g_Khi[BATCH*NH*SEQ*DH];
__device__ __nv_bfloat16 g_Klo[BATCH*NH*SEQ*DH];
__device__ __half        g_Vf[BATCH*NH*SEQ*DH];   // head-major, single f16
__device__ __half        g_Of[M_TOT*EMB];         // row-major, single f16

// ---------------------------------------------------------------------------
// PTX helpers (portable sm_80-class only)
// ---------------------------------------------------------------------------
__device__ __forceinline__ uint32_t smem_u32(const void* p) {
    uint32_t a;
    asm("{ .reg .u64 t; cvta.to.shared.u64 t, %1; cvt.u32.u64 %0, t; }" : "=r"(a) : "l"(p));
    return a;
}

#define CP_ASYNC16(dst, src) \
    asm volatile("cp.async.cg.shared.global [%0], [%1], 16;" :: "r"(dst), "l"(src))
#define CP_COMMIT() asm volatile("cp.async.commit_group;")
#define CP_WAIT0()  asm volatile("cp.async.wait_group 0;")
#define CP_WAIT1()  asm volatile("cp.async.wait_group 1;")

#define LDSM4(r, addr) \
    asm volatile("ldmatrix.sync.aligned.m8n8.x4.shared.b16 {%0,%1,%2,%3}, [%4];" \
        : "=r"((r)[0]), "=r"((r)[1]), "=r"((r)[2]), "=r"((r)[3]) : "r"(addr))
#define LDSM4T(r, addr) \
    asm volatile("ldmatrix.sync.aligned.m8n8.x4.trans.shared.b16 {%0,%1,%2,%3}, [%4];" \
        : "=r"((r)[0]), "=r"((r)[1]), "=r"((r)[2]), "=r"((r)[3]) : "r"(addr))

#define MMA_BF16(c, a, b0v, b1v) \
    asm volatile("mma.sync.aligned.m16n8k16.row.col.f32.bf16.bf16.f32 " \
        "{%0,%1,%2,%3}, {%4,%5,%6,%7}, {%8,%9}, {%0,%1,%2,%3};" \
        : "+f"((c)[0]), "+f"((c)[1]), "+f"((c)[2]), "+f"((c)[3]) \
        : "r"((a)[0]), "r"((a)[1]), "r"((a)[2]), "r"((a)[3]), "r"(b0v), "r"(b1v))

#define MMA_F16(c, a, b0v, b1v) \
    asm volatile("mma.sync.aligned.m16n8k16.row.col.f32.f16.f16.f32 " \
        "{%0,%1,%2,%3}, {%4,%5,%6,%7}, {%8,%9}, {%0,%1,%2,%3};" \
        : "+f"((c)[0]), "+f"((c)[1]), "+f"((c)[2]), "+f"((c)[3]) \
        : "r"((a)[0]), "r"((a)[1]), "r"((a)[2]), "r"((a)[3]), "r"(b0v), "r"(b1v))

__device__ __forceinline__ float fast_exp2(float x) {
    float r;
    asm("ex2.approx.ftz.f32 %0, %1;" : "=f"(r) : "f"(x));
    return r;
}

__device__ __forceinline__ uint32_t packbf2(float lo, float hi) {
    uint32_t r;
    asm("cvt.rn.bf16x2.f32 %0, %1, %2;" : "=r"(r) : "f"(hi), "f"(lo));
    return r;
}
__device__ __forceinline__ float bflo(uint32_t u) { return __uint_as_float(u << 16); }
__device__ __forceinline__ float bfhi(uint32_t u) { return __uint_as_float(u & 0xFFFF0000u); }

__device__ __forceinline__ uint32_t packh2(float a, float b) {
    __half2 h = __floats2half2_rn(a, b);
    return *(uint32_t*)&h;
}
__device__ __forceinline__ float hsum2(uint32_t u) {
    __half2 h = *(__half2*)&u;
    float2 f = __half22float2(h);
    return f.x + f.y;
}

__device__ __forceinline__ uint32_t swz(uint32_t off) {   // SW128 for 128B rows
    return off ^ ((off >> 3) & 0x70);
}
// Conflict-free swizzle for 64B rows: XOR keyed on row-pair (off>>7),
// granule(r,c) = 4r + (c ^ ((r>>1)&3)) mod 8 -> bijective over any
// 8-row ldmatrix phase at fixed column. (The r15 version keyed on off>>2
// was 2-way conflicted — root cause of the r15 regression.)
__device__ __forceinline__ uint32_t swz64p(uint32_t off) {
    return off ^ (((off >> 7) & 3) << 4);
}

// ---------------------------------------------------------------------------
// Fused conversion kernel: blocks [0,2048) convert X; [2048,2560) convert W.
// ---------------------------------------------------------------------------
__global__ void convert_all(const float* __restrict__ X,
                            const float* __restrict__ W0, const float* __restrict__ W1,
                            const float* __restrict__ W2, const float* __restrict__ W3)
{
    __shared__ float Wsm[64][129];
    const int tid = threadIdx.x;
    if (blockIdx.x < 2048) {
        int gid = blockIdx.x * 256 + tid;
        size_t base = (size_t)gid * 8;
        float4 v0 = *(const float4*)&X[base];
        float4 v1 = *(const float4*)&X[base + 4];
        float vs[8] = {v0.x, v0.y, v0.z, v0.w, v1.x, v1.y, v1.z, v1.w};
        __nv_bfloat16 h[8], l[8];
        __half f[8];
#pragma unroll
        for (int i = 0; i < 8; i++) {
            h[i] = __float2bfloat16(vs[i]);
            l[i] = __float2bfloat16(vs[i] - __bfloat162float(h[i]));
            f[i] = __float2half_rn(vs[i]);
        }
        *(uint4*)&g_Xhi[base] = *(uint4*)h;
        *(uint4*)&g_Xlo[base] = *(uint4*)l;
        *(uint4*)&g_Xf[base]  = *(uint4*)f;
        return;
    }

    int bi = blockIdx.x - 2048;
    int w = bi >> 7;
    int rest = bi & 127;
    int ntile = rest >> 4;
    int kc = rest & 15;
    const float* W = (w == 0) ? W0 : (w == 1) ? W1 : (w == 2) ? W2 : W3;

#pragma unroll
    for (int i = 0; i < 32; i++) {
        int lin = i * 256 + tid;
        int kr = lin >> 7;
        int nc = lin & 127;
        Wsm[kr][nc] = W[(size_t)(kc * 64 + kr) * EMB + ntile * 128 + nc];
    }
    __syncthreads();

#pragma unroll
    for (int j = 0; j < 4; j++) {
        int lin = j * 256 + tid;
        int nin = lin >> 3;
        int g = lin & 7;
        float vs[8];
#pragma unroll
        for (int i = 0; i < 8; i++) vs[i] = Wsm[g * 8 + i][nin];
        if (w < 2) {
            size_t base = ((size_t)(w * EMB + ntile * 128 + nin)) * EMB + kc * 64 + g * 8;
            __nv_bfloat16 h[8], l[8];
#pragma unroll
            for (int i = 0; i < 8; i++) {
                h[i] = __float2bfloat16(vs[i]);
                l[i] = __float2bfloat16(vs[i] - __bfloat162float(h[i]));
            }
            *(uint4*)&g_Whi[base] = *(uint4*)h;
            *(uint4*)&g_Wlo[base] = *(uint4*)l;
        } else {
            size_t base = ((size_t)((w - 2) * EMB + ntile * 128 + nin)) * EMB + kc * 64 + g * 8;
            __half h[8];
#pragma unroll
            for (int i = 0; i < 8; i++) h[i] = __float2half_rn(vs[i]);
            *(uint4*)&g_Wf[base] = *(uint4*)h;
        }
    }
}

// ---------------------------------------------------------------------------
// Merged QKV projection v3: 768 CTAs, 256 thr, CTA tile 128x128, BK=32,
// 64B rows with CONFLICT-FREE swz64p. Stage 32KB (QK), 3 stages = 96KB
// -> 2 CTAs/SM (sync bubbles of one CTA hidden by the other).
//   CTA [0,512):   bf16x3 (Q: z=0, K: z=1)
//   CTA [512,768): single-f16 V
// FP accumulation order identical to r12.
// ---------------------------------------------------------------------------
#define PT32 8192                        // 128 rows * 64B
#define PSTG_QK (4*PT32)                 // 32768
#define PSTG_V  (2*PT32)                 // 16384
#define PROJ_SMEM (3*PSTG_QK)            // 98304

__global__ __launch_bounds__(256, 2)
void proj_all()
{
    extern __shared__ __align__(128) char smem[];
    const uint32_t sb = smem_u32(smem);
    const int tid = threadIdx.x, lane = tid & 31, wid = tid >> 5;
    const int wm = wid & 3, wn = wid >> 2;        // 4m x 2n

    const uint32_t aBase = (wm * 32 + (lane & 15)) * 64 + (lane >> 4) * 16;
    const uint32_t bBase = (wn * 64 + (lane & 7) + ((lane >> 4) << 3)) * 64
                         + ((lane >> 3) & 1) * 16;
    const int lrow = tid >> 2;          // 0..63
    const int lseg = tid & 3;           // 16B segment in 64B row

    float acc[2][8][4];
#pragma unroll
    for (int i = 0; i < 2; i++)
#pragma unroll
        for (int j = 0; j < 8; j++)
#pragma unroll
            for (int q = 0; q < 4; q++) acc[i][j][q] = 0.0f;

    if (blockIdx.x < 512) {
        // ---------------- Q/K bf16x3 path ----------------
        const int z = blockIdx.x >> 8;
        const int r = blockIdx.x & 255;
        const int bx = r & 7, by = r >> 3;

        const __nv_bfloat16* Bhi = g_Whi + (size_t)z * EMB * EMB;
        const __nv_bfloat16* Blo = g_Wlo + (size_t)z * EMB * EMB;

        auto load_stage = [&](int c, int slot) {
            const int k0 = c * 32;
            const uint32_t st = sb + slot * PSTG_QK;
#pragma unroll
            for (int i = 0; i < 2; i++) {
                const int rr = i * 64 + lrow;
                const uint32_t d = swz64p(rr * 64 + lseg * 16);
                const size_t gi = (size_t)(by * 128 + rr) * EMB + k0 + lseg * 8;
                const size_t gw = (size_t)(bx * 128 + rr) * EMB + k0 + lseg * 8;
                CP_ASYNC16(st + d,            g_Xhi + gi);
                CP_ASYNC16(st + PT32 + d,     g_Xlo + gi);
                CP_ASYNC16(st + 2*PT32 + d,   Bhi + gw);
                CP_ASYNC16(st + 3*PT32 + d,   Blo + gw);
            }
            CP_COMMIT();
        };

        load_stage(0, 0);
        load_stage(1, 1);

        for (int c = 0; c < 32; c++) {
            CP_WAIT1();
            __syncthreads();
            if (c + 2 < 32) load_stage(c + 2, (c + 2) % 3);
            const uint32_t st = sb + (c % 3) * PSTG_QK;
            const uint32_t Ah = st, Al = st + PT32;
            const uint32_t Bh = st + 2*PT32, Bl = st + 3*PT32;

#pragma unroll
            for (int kc = 0; kc < 2; kc++) {
                const uint32_t kB = kc * 32;
                uint32_t ar[2][4], bh[4][4], bt[4][4];
                // bh + ah resident
#pragma unroll
                for (int ni = 0; ni < 4; ni++)
                    LDSM4(bh[ni], Bh + swz64p(bBase + ni * 1024 + kB));
#pragma unroll
                for (int mi = 0; mi < 2; mi++)
                    LDSM4(ar[mi], Ah + swz64p(aBase + mi * 1024 + kB));
                // hh pass
#pragma unroll
                for (int mi = 0; mi < 2; mi++)
#pragma unroll
                    for (int ni = 0; ni < 4; ni++) {
                        MMA_BF16(acc[mi][2*ni],   ar[mi], bh[ni][0], bh[ni][1]);
                        MMA_BF16(acc[mi][2*ni+1], ar[mi], bh[ni][2], bh[ni][3]);
                    }
                // hl pass (bl transient in bt)
#pragma unroll
                for (int ni = 0; ni < 4; ni++)
                    LDSM4(bt[ni], Bl + swz64p(bBase + ni * 1024 + kB));
#pragma unroll
                for (int mi = 0; mi < 2; mi++)
#pragma unroll
                    for (int ni = 0; ni < 4; ni++) {
                        MMA_BF16(acc[mi][2*ni],   ar[mi], bt[ni][0], bt[ni][1]);
                        MMA_BF16(acc[mi][2*ni+1], ar[mi], bt[ni][2], bt[ni][3]);
                    }
                // lh pass (al overwrites ar)
#pragma unroll
                for (int mi = 0; mi < 2; mi++)
                    LDSM4(ar[mi], Al + swz64p(aBase + mi * 1024 + kB));
#pragma unroll
                for (int mi = 0; mi < 2; mi++)
#pragma unroll
                    for (int ni = 0; ni < 4; ni++) {
                        MMA_BF16(acc[mi][2*ni],   ar[mi], bh[ni][0], bh[ni][1]);
                        MMA_BF16(acc[mi][2*ni+1], ar[mi], bh[ni][2], bh[ni][3]);
                    }
            }
        }
        __syncthreads();

        float* Cs = (float*)smem;            // [128][132] = 67584B < 98304
#pragma unroll
        for (int mi = 0; mi < 2; mi++)
#pragma unroll
            for (int nf = 0; nf < 8; nf++) {
                const int r0 = wm * 32 + mi * 16 + (lane >> 2);
                const int col = wn * 64 + nf * 8 + (lane & 3) * 2;
                *(float2*)&Cs[r0 * 132 + col]       = make_float2(acc[mi][nf][0], acc[mi][nf][1]);
                *(float2*)&Cs[(r0 + 8) * 132 + col] = make_float2(acc[mi][nf][2], acc[mi][nf][3]);
            }
        __syncthreads();

#pragma unroll
        for (int it = 0; it < 16; it++) {
            const int lin = it * 256 + tid;
            const int rr = lin >> 5;
            const int cg = (lin & 31) * 4;
            float4 v = *(const float4*)&Cs[rr * 132 + cg];
            const int m = by * 128 + rr;
            const int n = bx * 128 + cg;
            const int b = m >> 11, s = m & 2047, h = n >> 6, d = n & 63;
            __nv_bfloat16* dh = (z == 0) ? g_Qhi : g_Khi;
            __nv_bfloat16* dl = (z == 0) ? g_Qlo : g_Klo;
            uint32_t u0 = packbf2(v.x, v.y), u1 = packbf2(v.z, v.w);
            uint32_t l0 = packbf2(v.x - bflo(u0), v.y - bfhi(u0));
            uint32_t l1 = packbf2(v.z - bflo(u1), v.w - bfhi(u1));
            size_t addr = (((size_t)(b * NH + h)) * SEQ + s) * DH + d;
            *(uint2*)&dh[addr] = make_uint2(u0, u1);
            *(uint2*)&dl[addr] = make_uint2(l0, l1);
        }
    } else {
        // ---------------- V single-f16 path ----------------
        const int j = blockIdx.x - 512;
        const int bx = j & 7, by = j >> 3;
        const __half* Bf = g_Wf;

        auto load_stage = [&](int c, int slot) {
            const int k0 = c * 32;
            const uint32_t st = sb + slot * PSTG_V;
#pragma unroll
            for (int i = 0; i < 2; i++) {
                const int rr = i * 64 + lrow;
                const uint32_t d = swz64p(rr * 64 + lseg * 16);
                CP_ASYNC16(st + d,
                           g_Xf + (size_t)(by * 128 + rr) * EMB + k0 + lseg * 8);
                CP_ASYNC16(st + PT32 + d,
                           Bf + (size_t)(bx * 128 + rr) * EMB + k0 + lseg * 8);
            }
            CP_COMMIT();
        };

        load_stage(0, 0);
        load_stage(1, 1);

        for (int c = 0; c < 32; c++) {
            CP_WAIT1();
            __syncthreads();
            if (c + 2 < 32) load_stage(c + 2, (c + 2) % 3);
            const uint32_t st = sb + (c % 3) * PSTG_V;
            const uint32_t At = st, Bt = st + PT32;

#pragma unroll
            for (int kc = 0; kc < 2; kc++) {
                const uint32_t kB = kc * 32;
                uint32_t ar[2][4], bh[4][4];
#pragma unroll
                for (int ni = 0; ni < 4; ni++)
                    LDSM4(bh[ni], Bt + swz64p(bBase + ni * 1024 + kB));
#pragma unroll
                for (int mi = 0; mi < 2; mi++)
                    LDSM4(ar[mi], At + swz64p(aBase + mi * 1024 + kB));
#pragma unroll
                for (int mi = 0; mi < 2; mi++)
#pragma unroll
                    for (int ni = 0; ni < 4; ni++) {
                        MMA_F16(acc[mi][2*ni],   ar[mi], bh[ni][0], bh[ni][1]);
                        MMA_F16(acc[mi][2*ni+1], ar[mi], bh[ni][2], bh[ni][3]);
                    }
            }
        }
        __syncthreads();

        float* Cs = (float*)smem;
#pragma unroll
        for (int mi = 0; mi < 2; mi++)
#pragma unroll
            for (int nf = 0; nf < 8; nf++) {
                const int r0 = wm * 32 + mi * 16 + (lane >> 2);
                const int col = wn * 64 + nf * 8 + (lane & 3) * 2;
                *(float2*)&Cs[r0 * 132 + col]       = make_float2(acc[mi][nf][0], acc[mi][nf][1]);
                *(float2*)&Cs[(r0 + 8) * 132 + col] = make_float2(acc[mi][nf][2], acc[mi][nf][3]);
            }
        __syncthreads();

#pragma unroll
        for (int it = 0; it < 16; it++) {
            const int lin = it * 256 + tid;
            const int rr = lin >> 5;
            const int cg = (lin & 31) * 4;
            float4 v = *(const float4*)&Cs[rr * 132 + cg];
            const int m = by * 128 + rr;
            const int n = bx * 128 + cg;
            const int b = m >> 11, s = m & 2047, h = n >> 6, d = n & 63;
            size_t addr = (((size_t)(b * NH + h)) * SEQ + s) * DH + d;
            *(uint2*)&g_Vf[addr] = make_uint2(packh2(v.x, v.y), packh2(v.z, v.w));
        }
    }
}

// ---------------------------------------------------------------------------
// gemm_o: single-f16 GEMM (r12 — frozen).
// ---------------------------------------------------------------------------
#define PA_TILE 16384                    // 128 rows * 128B
#define GO_STAGE (2*PA_TILE)             // 32768
#define GO_SMEM  (3*GO_STAGE)            // 98304

__global__ __launch_bounds__(256, 2)
void gemm_o(float* __restrict__ Cout)
{
    extern __shared__ __align__(128) char smem[];
    const uint32_t sb = smem_u32(smem);
    const int tid = threadIdx.x, lane = tid & 31, wid = tid >> 5;
    const int wm = wid & 3, wn = wid >> 2;
    const int bx = blockIdx.x, by = blockIdx.y;

    const __half* Bf = g_Wf + (size_t)EMB * EMB;   // Wo

    const uint32_t aBase = (wm * 32 + (lane & 15)) * 128 + (lane >> 4) * 16;
    const uint32_t bBase = (wn * 64 + (lane & 7) + ((lane >> 4) << 3)) * 128
                         + ((lane >> 3) & 1) * 16;
    const int lrow = tid >> 3;
    const int lseg = tid & 7;

    float acc[2][8][4];
#pragma unroll
    for (int i = 0; i < 2; i++)
#pragma unroll
        for (int j = 0; j < 8; j++)
#pragma unroll
            for (int q = 0; q < 4; q++) acc[i][j][q] = 0.0f;

    auto load_stage = [&](int c, int slot) {
        const int k0 = c * 64;
        const uint32_t st = sb + slot * GO_STAGE;
#pragma unroll
        for (int i = 0; i < 4; i++) {
            const int rr = i * 32 + lrow;
            const uint32_t d = swz(rr * 128 + lseg * 16);
            CP_ASYNC16(st + d,
                       g_Of + (size_t)(by * 128 + rr) * EMB + k0 + lseg * 8);
            CP_ASYNC16(st + PA_TILE + d,
                       Bf + (size_t)(bx * 128 + rr) * EMB + k0 + lseg * 8);
        }
        CP_COMMIT();
    };

    load_stage(0, 0);
    load_stage(1, 1);

    for (int c = 0; c < 16; c++) {
        CP_WAIT1();
        __syncthreads();
        if (c + 2 < 16) load_stage(c + 2, (c + 2) % 3);
        const uint32_t st = sb + (c % 3) * GO_STAGE;
        const uint32_t At = st, Bt = st + PA_TILE;

#pragma unroll
        for (int kc = 0; kc < 4; kc++) {
            const uint32_t kB = kc * 32;
            uint32_t ar[2][4], bh[4][4];
#pragma unroll
            for (int ni = 0; ni < 4; ni++)
                LDSM4(bh[ni], Bt + swz(bBase + ni * 2048 + kB));
#pragma unroll
            for (int mi = 0; mi < 2; mi++)
                LDSM4(ar[mi], At + swz(aBase + mi * 2048 + kB));
#pragma unroll
            for (int mi = 0; mi < 2; mi++)
#pragma unroll
                for (int ni = 0; ni < 4; ni++) {
                    MMA_F16(acc[mi][2*ni],   ar[mi], bh[ni][0], bh[ni][1]);
                    MMA_F16(acc[mi][2*ni+1], ar[mi], bh[ni][2], bh[ni][3]);
                }
        }
    }
    __syncthreads();

    float* Cs = (float*)smem;            // [128][132]
#pragma unroll
    for (int mi = 0; mi < 2; mi++)
#pragma unroll
        for (int nf = 0; nf < 8; nf++) {
            const int r0 = wm * 32 + mi * 16 + (lane >> 2);
            const int col = wn * 64 + nf * 8 + (lane & 3) * 2;
            *(float2*)&Cs[r0 * 132 + col]       = make_float2(acc[mi][nf][0], acc[mi][nf][1]);
            *(float2*)&Cs[(r0 + 8) * 132 + col] = make_float2(acc[mi][nf][2], acc[mi][nf][3]);
        }
    __syncthreads();

#pragma unroll
    for (int it = 0; it < 16; it++) {
        const int lin = it * 256 + tid;
        const int rr = lin >> 5;
        const int cg = (lin & 31) * 4;
        float4 v = *(const float4*)&Cs[rr * 132 + cg];
        const int m = by * 128 + rr;
        const int n = bx * 128 + cg;
        *(float4*)&Cout[(size_t)m * EMB + n] = v;
    }
}

// ---------------------------------------------------------------------------
// Flash attention (r12 — frozen, best known): 128 q-rows, 128-row KV tiles,
// QK bf16x3, PV f16 P x f16 V (l over rounded P).
// ---------------------------------------------------------------------------
#define KV_STAGE 49152      // Kh 16KB + Kl 16KB + Vf 16KB
#define FL_SMEM (32768 + 2*KV_STAGE)   // 131072
#define CEXP 0.18033688f    // 0.125 * log2(e)

__global__ __launch_bounds__(256, 1)
void flash_mma()
{
    const int qi = (int)gridDim.x - 1 - blockIdx.x;   // heavy tiles first
    const int h = blockIdx.y, b = blockIdx.z;
    const int tid = threadIdx.x, lane = tid & 31, w = tid >> 5;
    extern __shared__ __align__(128) char smf[];
    const uint32_t sb = smem_u32(smf);
    const uint32_t Qh_ = sb, Ql_ = sb + 16384;

    const size_t head = ((size_t)(b * NH + h)) * SEQ * DH;
    const __nv_bfloat16* Qhg = g_Qhi + head;
    const __nv_bfloat16* Qlg = g_Qlo + head;
    const __nv_bfloat16* Khg = g_Khi + head;
    const __nv_bfloat16* Klg = g_Klo + head;
    const __half*        Vfg = g_Vf  + head;
    const int qbase = qi * 128;

#pragma unroll
    for (int i = 0; i < 4; i++) {
        int lin = i * 256 + tid;
        int r = lin >> 3, c = lin & 7;
        uint32_t off = swz(r * 128 + c * 16);
        CP_ASYNC16(Qh_ + off, Qhg + (size_t)(qbase + r) * 64 + c * 8);
        CP_ASYNC16(Ql_ + off, Qlg + (size_t)(qbase + r) * 64 + c * 8);
    }
    CP_COMMIT();

    auto load_kv = [&](int jt, int slot) {
        const uint32_t st = sb + 32768 + slot * KV_STAGE;
#pragma unroll
        for (int i = 0; i < 4; i++) {
            int lin = i * 256 + tid;
            int r = lin >> 3, c = lin & 7;
            uint32_t off = swz(r * 128 + c * 16);
            size_t gidx = (size_t)(jt * 128 + r) * 64 + c * 8;
            CP_ASYNC16(st + off,             Khg + gidx);
            CP_ASYNC16(st + 16384 + off,     Klg + gidx);
            CP_ASYNC16(st + 32768 + off,     Vfg + gidx);
        }
        CP_COMMIT();
    };

    load_kv(0, 0);
    CP_WAIT1();
    __syncthreads();

    uint32_t qh[4][4], ql[4][4];
    const uint32_t qoff = (w * 16 + (lane & 15)) * 128 + (lane >> 4) * 16;
#pragma unroll
    for (int kc = 0; kc < 4; kc++) {
        LDSM4(qh[kc], Qh_ + swz(qoff + kc * 32));
        LDSM4(ql[kc], Ql_ + swz(qoff + kc * 32));
    }

    float o_[8][4];
#pragma unroll
    for (int i = 0; i < 8; i++)
#pragma unroll
        for (int j = 0; j < 4; j++) o_[i][j] = 0.0f;
    float mrow[2] = {-3e38f, -3e38f};
    float lrow[2] = {0.0f, 0.0f};

    const int rA = qbase + w * 16 + (lane >> 2);
    const int rB = rA + 8;
    const uint32_t kOffBase = ((lane & 7) + ((lane >> 4) << 3)) * 128 + ((lane >> 3) & 1) * 16;
    const uint32_t vOffBase = (lane & 15) * 128 + (lane >> 4) * 16;

    for (int jt = 0; jt <= qi; jt++) {
        CP_WAIT0();
        __syncthreads();
        if (jt < qi) load_kv(jt + 1, (jt + 1) & 1);
        const uint32_t st = sb + 32768 + (jt & 1) * KV_STAGE;
        const uint32_t Kh_ = st, Kl_ = st + 16384, Vf_ = st + 32768;

        float s_[16][4];
#pragma unroll
        for (int i = 0; i < 16; i++)
#pragma unroll
            for (int j = 0; j < 4; j++) s_[i][j] = 0.0f;

#pragma unroll
        for (int tp = 0; tp < 4; tp++) {
#pragma unroll
            for (int kc = 0; kc < 4; kc++) {
                const uint32_t addrA = swz((2*tp)   * 16 * 128 + kOffBase + kc * 32);
                const uint32_t addrB = swz((2*tp+1) * 16 * 128 + kOffBase + kc * 32);
                uint32_t bha[4], bla[4], bhb[4], blb[4];
                LDSM4(bha, Kh_ + addrA);
                LDSM4(bhb, Kh_ + addrB);
                LDSM4(bla, Kl_ + addrA);
                LDSM4(blb, Kl_ + addrB);
                MMA_BF16(s_[4*tp],     qh[kc], bha[0], bha[1]);
                MMA_BF16(s_[4*tp + 1], qh[kc], bha[2], bha[3]);
                MMA_BF16(s_[4*tp + 2], qh[kc], bhb[0], bhb[1]);
                MMA_BF16(s_[4*tp + 3], qh[kc], bhb[2], bhb[3]);
                MMA_BF16(s_[4*tp],     ql[kc], bha[0], bha[1]);
                MMA_BF16(s_[4*tp + 1], ql[kc], bha[2], bha[3]);
                MMA_BF16(s_[4*tp + 2], ql[kc], bhb[0], bhb[1]);
                MMA_BF16(s_[4*tp + 3], ql[kc], bhb[2], bhb[3]);
                MMA_BF16(s_[4*tp],     qh[kc], bla[0], bla[1]);
                MMA_BF16(s_[4*tp + 1], qh[kc], bla[2], bla[3]);
                MMA_BF16(s_[4*tp + 2], qh[kc], blb[0], blb[1]);
                MMA_BF16(s_[4*tp + 3], qh[kc], blb[2], blb[3]);
            }
        }

        if (jt == qi) {
#pragma unroll
            for (int nf = 0; nf < 16; nf++) {
                const int colg = jt * 128 + nf * 8 + (lane & 3) * 2;
                if (colg     > rA) s_[nf][0] = -3e38f;
                if (colg + 1 > rA) s_[nf][1] = -3e38f;
                if (colg     > rB) s_[nf][2] = -3e38f;
                if (colg + 1 > rB) s_[nf][3] = -3e38f;
            }
        }

        float mx0 = -3e38f, mx1 = -3e38f;
#pragma unroll
        for (int nf = 0; nf < 16; nf++) {
            mx0 = fmaxf(mx0, fmaxf(s_[nf][0], s_[nf][1]));
            mx1 = fmaxf(mx1, fmaxf(s_[nf][2], s_[nf][3]));
        }
        mx0 = fmaxf(mx0, __shfl_xor_sync(0xffffffffu, mx0, 1));
        mx0 = fmaxf(mx0, __shfl_xor_sync(0xffffffffu, mx0, 2));
        mx1 = fmaxf(mx1, __shfl_xor_sync(0xffffffffu, mx1, 1));
        mx1 = fmaxf(mx1, __shfl_xor_sync(0xffffffffu, mx1, 2));
        const float mn0 = fmaxf(mrow[0], mx0);
        const float mn1 = fmaxf(mrow[1], mx1);
        const float c0 = fast_exp2((mrow[0] - mn0) * CEXP);
        const float c1 = fast_exp2((mrow[1] - mn1) * CEXP);
        mrow[0] = mn0; mrow[1] = mn1;

        uint32_t ph[8][4];
        float rs0 = 0.0f, rs1 = 0.0f;
#pragma unroll
        for (int j = 0; j < 8; j++) {
            const float p00 = fast_exp2((s_[2*j][0]   - mn0) * CEXP);
            const float p01 = fast_exp2((s_[2*j][1]   - mn0) * CEXP);
            const float p10 = fast_exp2((s_[2*j][2]   - mn1) * CEXP);
            const float p11 = fast_exp2((s_[2*j][3]   - mn1) * CEXP);
            const float p20 = fast_exp2((s_[2*j+1][0] - mn0) * CEXP);
            const float p21 = fast_exp2((s_[2*j+1][1] - mn0) * CEXP);
            const float p30 = fast_exp2((s_[2*j+1][2] - mn1) * CEXP);
            const float p31 = fast_exp2((s_[2*j+1][3] - mn1) * CEXP);
            ph[j][0] = packh2(p00, p01);
            ph[j][1] = packh2(p10, p11);
            ph[j][2] = packh2(p20, p21);
            ph[j][3] = packh2(p30, p31);
            rs0 += hsum2(ph[j][0]) + hsum2(ph[j][2]);
            rs1 += hsum2(ph[j][1]) + hsum2(ph[j][3]);
        }
        rs0 += __shfl_xor_sync(0xffffffffu, rs0, 1);
        rs0 += __shfl_xor_sync(0xffffffffu, rs0, 2);
        rs1 += __shfl_xor_sync(0xffffffffu, rs1, 1);
        rs1 += __shfl_xor_sync(0xffffffffu, rs1, 2);
        lrow[0] = lrow[0] * c0 + rs0;
        lrow[1] = lrow[1] * c1 + rs1;
#pragma unroll
        for (int nf = 0; nf < 8; nf++) {
            o_[nf][0] *= c0; o_[nf][1] *= c0;
            o_[nf][2] *= c1; o_[nf][3] *= c1;
        }

#pragma unroll
        for (int j = 0; j < 8; j++) {
#pragma unroll
            for (int t = 0; t < 4; t++) {
                uint32_t vf[4];
                LDSM4T(vf, Vf_ + swz(j * 16 * 128 + vOffBase + t * 32));
                MMA_F16(o_[2 * t],     ph[j], vf[0], vf[1]);
                MMA_F16(o_[2 * t + 1], ph[j], vf[2], vf[3]);
            }
        }
    }

    const float iA = 1.0f / lrow[0];
    const float iB = 1.0f / lrow[1];
    const size_t rowA = (size_t)(b * SEQ + rA) * EMB + h * 64;
    const size_t rowB = (size_t)(b * SEQ + rB) * EMB + h * 64;
#pragma unroll
    for (int nf = 0; nf < 8; nf++) {
        const int d = nf * 8 + (lane & 3) * 2;
        *(uint32_t*)&g_Of[rowA + d] = packh2(o_[nf][0] * iA, o_[nf][1] * iA);
        *(uint32_t*)&g_Of[rowB + d] = packh2(o_[nf][2] * iB, o_[nf][3] * iB);
    }
}

// ---------------------------------------------------------------------------
extern "C" void kernel_launch(void* const* d_in, const int* in_sizes, int n_in,
                              void* d_out, int out_size)
{
    const float* x  = (const float*)d_in[0];
    const float* Wq = (const float*)d_in[1];
    const float* Wk = (const float*)d_in[2];
    const float* Wv = (const float*)d_in[3];
    const float* Wo = (const float*)d_in[4];
    float* out = (float*)d_out;

    cudaFuncSetAttribute(proj_all,
                         cudaFuncAttributeMaxDynamicSharedMemorySize, PROJ_SMEM);
    cudaFuncSetAttribute(gemm_o,
                         cudaFuncAttributeMaxDynamicSharedMemorySize, GO_SMEM);
    cudaFuncSetAttribute(flash_mma,
                         cudaFuncAttributeMaxDynamicSharedMemorySize, FL_SMEM);

    // Convert X (bf16 hi/lo + f16) and W (Wq/Wk bf16 hi/lo, Wv/Wo f16)
    convert_all<<<2560, 256>>>(x, Wq, Wk, Wv, Wo);

    // Q,K (bf16x3) + V (f16) projections, BK=32, conflict-free swz64p, 2 CTAs/SM
    proj_all<<<768, 256, PROJ_SMEM>>>();

    // Flash attention (r12 frozen) -> Of
    flash_mma<<<dim3(SEQ/128, NH, BATCH), 256, FL_SMEM>>>();

    // Output projection (single f16) -> fp32 out
    gemm_o<<<dim3(8, 32), 256, GO_SMEM>>>(out);
}